// round 3
// baseline (speedup 1.0000x reference)
#include <cuda_runtime.h>
#include <math.h>

// Problem constants
#define BB 64     // batch
#define PP 16     // pos tags
#define TT 256    // timesteps
#define II 256    // embed dim
#define HH 512    // hidden
#define OO 5      // output
#define KK (PP*II)   // 4096
#define MM (BB*TT)   // 16384
#define NN (4*HH)    // 2048

// ---------------- scratch (device globals; no allocation allowed) ------------
__device__ float g_pre[TT * 4 * BB * HH];    // [t][gate][b][h]  134 MB
__device__ float g_whT[4 * HH * HH];         // [gate][h][k]     4 MB
__device__ float g_h[2][BB * HH];
__device__ float g_c[BB * HH];

// ---------------- init: zero h0, c0 ------------------------------------------
__global__ void init_state() {
    int v = blockIdx.x * 256 + threadIdx.x;
    if (v < BB * HH) { g_h[0][v] = 0.f; g_c[v] = 0.f; }
}

// ---------------- transpose Wh -> [gate][h][k] -------------------------------
__global__ void transpose_wh(const float* __restrict__ Wf, const float* __restrict__ Wi,
                             const float* __restrict__ Wg, const float* __restrict__ Wo) {
    int v = blockIdx.x * 256 + threadIdx.x;   // < 4*512*512
    int g = v >> 18;
    int h = (v >> 9) & 511;
    int k = v & 511;
    const float* W = (g == 0) ? Wf : (g == 1) ? Wi : (g == 2) ? Wg : Wo;
    g_whT[v] = W[k * HH + h];
}

// ---------------- Kernel A: gathered SGEMM -> pre-activations ---------------
// C[m, n], m = t*64 + b (M=16384), n = gate*512 + h (N=2048)
// A[m, k] = emb[x[b,p,t], i] (0 if idx==0), k = p*256 + i
// B[k, n] = W_gate[(p*I+i)*H + h]   (W_x is (P,I,H) row-major => [K,H] row-major)
#define Bb_M 128
#define Bb_N 128
#define Bb_K 32

__global__ void __launch_bounds__(256, 2)
gemm_pre(const int* __restrict__ x, const float* __restrict__ emb,
         const float* __restrict__ Wf, const float* __restrict__ Wi,
         const float* __restrict__ Wg, const float* __restrict__ Wo,
         const float* __restrict__ bf, const float* __restrict__ bi,
         const float* __restrict__ bg, const float* __restrict__ bo) {
    __shared__ float As[Bb_K][132];     // [k][m-row], padded rows (528 B, 16B-aligned)
    __shared__ float Bs[Bb_K][Bb_N];    // [k][n-col]
    __shared__ int   sIdx[PP][Bb_M];    // [p][m-row] token indices for this m-tile

    int tid = threadIdx.x;
    int m0 = blockIdx.y * Bb_M;
    int n0 = blockIdx.x * Bb_N;
    int gate = n0 >> 9;         // BN=128 => block lies entirely within one gate
    int h0 = n0 & 511;
    const float* W    = (gate == 0) ? Wf : (gate == 1) ? Wi : (gate == 2) ? Wg : Wo;
    const float* bias = (gate == 0) ? bf : (gate == 1) ? bi : (gate == 2) ? bg : bo;

    // cache the 128 rows' token indices for all P tags
    for (int v = tid; v < PP * Bb_M; v += 256) {
        int p = v >> 7, r = v & 127;
        int m = m0 + r;
        int t = m >> 6, b = m & 63;
        sIdx[p][r] = x[(b * PP + p) * TT + t];
    }
    __syncthreads();

    float acc[8][8];
    #pragma unroll
    for (int a = 0; a < 8; a++)
        #pragma unroll
        for (int b2 = 0; b2 < 8; b2++) acc[a][b2] = 0.f;

    int tx = tid & 15;   // n micro-tile
    int ty = tid >> 4;   // m micro-tile
    int kc = tid & 31;   // A staging: k within tile
    int r0 = tid >> 5;   // A staging: row base (0..7)
    int nc  = tid & 127; // B staging: col
    int kr0 = tid >> 7;  // B staging: k base (0..1)

    for (int k0 = 0; k0 < KK; k0 += Bb_K) {
        int p  = k0 >> 8;
        int i0 = k0 & 255;
        // stage A (gathered from embedding table; padding_idx=0 -> zero row)
        #pragma unroll
        for (int it = 0; it < 16; it++) {
            int r = r0 + it * 8;
            int idx = sIdx[p][r];
            As[kc][r] = (idx != 0) ? emb[idx * II + i0 + kc] : 0.f;
        }
        // stage B
        #pragma unroll
        for (int it = 0; it < 16; it++) {
            int kk2 = kr0 + it * 2;
            Bs[kk2][nc] = W[(size_t)(k0 + kk2) * HH + h0 + nc];
        }
        __syncthreads();
        #pragma unroll
        for (int kk = 0; kk < Bb_K; kk++) {
            float4 a0 = *(const float4*)&As[kk][ty * 8];
            float4 a1 = *(const float4*)&As[kk][ty * 8 + 4];
            float4 b0 = *(const float4*)&Bs[kk][tx * 8];
            float4 b1 = *(const float4*)&Bs[kk][tx * 8 + 4];
            float a[8] = {a0.x, a0.y, a0.z, a0.w, a1.x, a1.y, a1.z, a1.w};
            float b[8] = {b0.x, b0.y, b0.z, b0.w, b1.x, b1.y, b1.z, b1.w};
            #pragma unroll
            for (int um = 0; um < 8; um++)
                #pragma unroll
                for (int un = 0; un < 8; un++)
                    acc[um][un] += a[um] * b[un];
        }
        __syncthreads();
    }
    // epilogue: + bias, scatter to pre[t][gate][b][h]
    #pragma unroll
    for (int um = 0; um < 8; um++) {
        int m = m0 + ty * 8 + um;
        int t = m >> 6, b = m & 63;
        float* dst = g_pre + ((size_t)(t * 4 + gate) * 64 + b) * 512 + h0;
        #pragma unroll
        for (int un = 0; un < 8; un++) {
            int h = tx * 8 + un;
            dst[h] = acc[um][un] + bias[h0 + h];
        }
    }
}

// ---------------- LSTM step: gates = pre[t] + h @ Wh; update c,h ------------
// grid 128 blocks x 256 thr. Block handles 4 h-cols (all 64 b, 4 gates).
__global__ void __launch_bounds__(256, 1)
lstm_step(int t) {
    __shared__ float sW[4][4][HH + 4];  // ~33 KB: Wh^T slice [gate][h_local][k], padded
    __shared__ float sh[64][36];        // h_prev tile [b][k-local], padded

    int tid = threadIdx.x;
    int bh0 = blockIdx.x * 4;
    const float* h_prev = g_h[t & 1];
    float*       h_next = g_h[(t + 1) & 1];
    const float* pre_t  = g_pre + (size_t)t * 4 * BB * HH;

    // load W slice (whole K) once: 4 gates x 4 h-cols x 512 k
    for (int v = tid; v < 2048; v += 256) {      // float4 count: 4*4*512/4
        int gi = v >> 7;            // 0..15 : (g, hl)
        int g  = gi >> 2, hl = gi & 3;
        int k4 = v & 127;
        const float4* src = (const float4*)(g_whT + (size_t)g * HH * HH + (size_t)(bh0 + hl) * HH);
        ((float4*)&sW[g][hl][0])[k4] = src[k4];
    }

    int hl = tid & 3;
    int b  = tid >> 2;
    float acc[4];
    #pragma unroll
    for (int g = 0; g < 4; g++)
        acc[g] = pre_t[((g * 64) + b) * 512 + bh0 + hl];

    __syncthreads();

    for (int k0 = 0; k0 < HH; k0 += 32) {
        // stage h_prev[:, k0:k0+32]
        for (int v = tid; v < 512; v += 256) {
            int row = v >> 3, c4 = v & 7;
            float4 hv = *(const float4*)&h_prev[row * HH + k0 + c4 * 4];
            *(float4*)&sh[row][c4 * 4] = hv;
        }
        __syncthreads();
        #pragma unroll
        for (int kk = 0; kk < 32; kk += 4) {
            float4 hv = *(const float4*)&sh[b][kk];
            #pragma unroll
            for (int g = 0; g < 4; g++) {
                float4 wv = *(const float4*)&sW[g][hl][k0 + kk];
                acc[g] += hv.x * wv.x + hv.y * wv.y + hv.z * wv.z + hv.w * wv.w;
            }
        }
        __syncthreads();
    }

    int off = b * HH + bh0 + hl;
    float f  = 1.f / (1.f + expf(-acc[0]));
    float ii = 1.f / (1.f + expf(-acc[1]));
    float gg = tanhf(acc[2]);
    float oo = 1.f / (1.f + expf(-acc[3]));
    float c = f * g_c[off] + ii * gg;
    g_c[off] = c;
    h_next[off] = oo * tanhf(c);
}

// ---------------- final: out = h @ W_lin + b_lin; emit (out, h, c) ----------
__global__ void final_k(const float* __restrict__ Wlin, const float* __restrict__ blin,
                        float* __restrict__ out) {
    int b = blockIdx.x;
    int tid = threadIdx.x;
    const float* h = g_h[0];   // after 256 steps, (255+1)&1 == 0
    const float* c = g_c;

    float* out_h = out + BB * OO;
    float* out_c = out + BB * OO + BB * HH;
    for (int v = tid; v < HH; v += 256) {
        out_h[b * HH + v] = h[b * HH + v];
        out_c[b * HH + v] = c[b * HH + v];
    }

    __shared__ float red[256 * OO];
    float p[OO];
    #pragma unroll
    for (int o = 0; o < OO; o++) p[o] = 0.f;
    for (int k = tid; k < HH; k += 256) {
        float hv = h[b * HH + k];
        #pragma unroll
        for (int o = 0; o < OO; o++) p[o] += hv * Wlin[k * OO + o];
    }
    #pragma unroll
    for (int o = 0; o < OO; o++) red[tid * OO + o] = p[o];
    __syncthreads();
    for (int s = 128; s > 0; s >>= 1) {
        if (tid < s)
            #pragma unroll
            for (int o = 0; o < OO; o++) red[tid * OO + o] += red[(tid + s) * OO + o];
        __syncthreads();
    }
    if (tid < OO) out[b * OO + tid] = red[tid] + blin[tid];
}

// ---------------- host launcher ---------------------------------------------
extern "C" void kernel_launch(void* const* d_in, const int* in_sizes, int n_in,
                              void* d_out, int out_size) {
    const int*   x    = (const int*)d_in[0];
    const float* emb  = (const float*)d_in[1];
    const float* Wfx  = (const float*)d_in[2];
    const float* Wfh  = (const float*)d_in[3];
    const float* bf   = (const float*)d_in[4];
    const float* Wix  = (const float*)d_in[5];
    const float* Wih  = (const float*)d_in[6];
    const float* bi   = (const float*)d_in[7];
    const float* Wgx  = (const float*)d_in[8];
    const float* Wgh  = (const float*)d_in[9];
    const float* bg   = (const float*)d_in[10];
    const float* Wox  = (const float*)d_in[11];
    const float* Woh  = (const float*)d_in[12];
    const float* bo   = (const float*)d_in[13];
    const float* Wlin = (const float*)d_in[14];
    const float* blin = (const float*)d_in[15];
    float* out = (float*)d_out;

    init_state<<<128, 256>>>();
    transpose_wh<<<4096, 256>>>(Wfh, Wih, Wgh, Woh);
    gemm_pre<<<dim3(NN / Bb_N, MM / Bb_M), 256>>>(x, emb, Wfx, Wix, Wgx, Wox,
                                                  bf, bi, bg, bo);
    for (int t = 0; t < TT; t++) lstm_step<<<128, 256>>>(t);
    final_k<<<BB, 256>>>(Wlin, blin, out);
}

// round 4
// speedup vs baseline: 1.3445x; 1.3445x over previous
#include <cuda_runtime.h>
#include <math.h>

// Problem constants
#define BB 64     // batch
#define PP 16     // pos tags
#define TT 256    // timesteps
#define II 256    // embed dim
#define HH 512    // hidden
#define OO 5      // output
#define KK (PP*II)   // 4096
#define MM (BB*TT)   // 16384
#define NN (4*HH)    // 2048

#define NBLK 128     // persistent grid size (all co-resident on 148 SMs)

// ---------------- scratch (device globals; no allocation allowed) ------------
__device__ float g_pre[(size_t)TT * 4 * BB * HH];  // [t][gate][b][h]  134 MB
__device__ float g_h[2][BB * HH];                  // h double buffer
__device__ float g_c[BB * HH];                     // final c (written once at end)

// grid barrier state (self-resetting; gen monotonic across replays)
__device__ unsigned g_count = 0;
__device__ unsigned g_gen = 0;

// ---------------- Kernel A: gathered SGEMM -> pre-activations ---------------
// C[m, n], m = t*64 + b (M=16384), n = gate*512 + h (N=2048)
// A[m, k] = emb[x[b,p,t], i] (0 if idx==0), k = p*256 + i
// B[k, n] = W_gate[(p*I+i)*H + h]
#define Bb_M 128
#define Bb_N 128
#define Bb_K 32

__global__ void __launch_bounds__(256, 2)
gemm_pre(const int* __restrict__ x, const float* __restrict__ emb,
         const float* __restrict__ Wf, const float* __restrict__ Wi,
         const float* __restrict__ Wg, const float* __restrict__ Wo,
         const float* __restrict__ bf, const float* __restrict__ bi,
         const float* __restrict__ bg, const float* __restrict__ bo) {
    __shared__ float As[Bb_K][132];
    __shared__ float Bs[Bb_K][Bb_N];
    __shared__ int   sIdx[PP][Bb_M];

    int tid = threadIdx.x;
    int m0 = blockIdx.y * Bb_M;
    int n0 = blockIdx.x * Bb_N;
    int gate = n0 >> 9;
    int h0 = n0 & 511;
    const float* W    = (gate == 0) ? Wf : (gate == 1) ? Wi : (gate == 2) ? Wg : Wo;
    const float* bias = (gate == 0) ? bf : (gate == 1) ? bi : (gate == 2) ? bg : bo;

    for (int v = tid; v < PP * Bb_M; v += 256) {
        int p = v >> 7, r = v & 127;
        int m = m0 + r;
        int t = m >> 6, b = m & 63;
        sIdx[p][r] = x[(b * PP + p) * TT + t];
    }
    __syncthreads();

    float acc[8][8];
    #pragma unroll
    for (int a = 0; a < 8; a++)
        #pragma unroll
        for (int b2 = 0; b2 < 8; b2++) acc[a][b2] = 0.f;

    int tx = tid & 15;
    int ty = tid >> 4;
    int kc = tid & 31;
    int r0 = tid >> 5;
    int nc  = tid & 127;
    int kr0 = tid >> 7;

    for (int k0 = 0; k0 < KK; k0 += Bb_K) {
        int p  = k0 >> 8;
        int i0 = k0 & 255;
        #pragma unroll
        for (int it = 0; it < 16; it++) {
            int r = r0 + it * 8;
            int idx = sIdx[p][r];
            As[kc][r] = (idx != 0) ? emb[idx * II + i0 + kc] : 0.f;
        }
        #pragma unroll
        for (int it = 0; it < 16; it++) {
            int kk2 = kr0 + it * 2;
            Bs[kk2][nc] = W[(size_t)(k0 + kk2) * HH + h0 + nc];
        }
        __syncthreads();
        #pragma unroll
        for (int kk = 0; kk < Bb_K; kk++) {
            float4 a0 = *(const float4*)&As[kk][ty * 8];
            float4 a1 = *(const float4*)&As[kk][ty * 8 + 4];
            float4 b0 = *(const float4*)&Bs[kk][tx * 8];
            float4 b1 = *(const float4*)&Bs[kk][tx * 8 + 4];
            float a[8] = {a0.x, a0.y, a0.z, a0.w, a1.x, a1.y, a1.z, a1.w};
            float b[8] = {b0.x, b0.y, b0.z, b0.w, b1.x, b1.y, b1.z, b1.w};
            #pragma unroll
            for (int um = 0; um < 8; um++)
                #pragma unroll
                for (int un = 0; un < 8; un++)
                    acc[um][un] += a[um] * b[un];
        }
        __syncthreads();
    }
    #pragma unroll
    for (int um = 0; um < 8; um++) {
        int m = m0 + ty * 8 + um;
        int t = m >> 6, b = m & 63;
        float* dst = g_pre + ((size_t)(t * 4 + gate) * 64 + b) * 512 + h0;
        #pragma unroll
        for (int un = 0; un < 8; un++) {
            int h = tx * 8 + un;
            dst[h] = acc[um][un] + bias[h0 + h];
        }
    }
}

// ---------------- persistent LSTM recurrence ---------------------------------
// Grid: 128 blocks x 256 threads, all co-resident. One launch covers all 256
// timesteps; grid barrier between steps.
//
// Block bx: h-group hg = bx>>1 (8 h-cols, h0 = hg*8), b-group bg = bx&1
// (32 batches, b0 = bg*32). Block columns: col = gate*8 + hl, col = 0..31.
//
// smem: sW[32 cols][516]  (weight slice, loaded ONCE)
//       sh[32 b][516]     (h_prev tile, staged per step)
//       sG[32 b][33]      (gate pre-activations for pointwise phase)
#define SW_F (32 * 516)
#define SH_F (32 * 516)
#define SG_F (32 * 33)
#define SMEM_FLOATS (SW_F + SH_F + SG_F)
#define SMEM_BYTES (SMEM_FLOATS * 4)

__device__ __forceinline__ void grid_barrier() {
    __threadfence();
    __syncthreads();
    if (threadIdx.x == 0) {
        unsigned gen = *((volatile unsigned*)&g_gen);
        if (atomicAdd(&g_count, 1u) == NBLK - 1) {
            g_count = 0;
            __threadfence();
            *((volatile unsigned*)&g_gen) = gen + 1;
        } else {
            while (*((volatile unsigned*)&g_gen) == gen) { }
        }
    }
    __syncthreads();
}

__global__ void __launch_bounds__(256, 1)
lstm_persist(const float* __restrict__ Wfh, const float* __restrict__ Wih,
             const float* __restrict__ Wgh, const float* __restrict__ Woh) {
    extern __shared__ float sm[];
    float* sW = sm;                 // [32][516]
    float* sh = sm + SW_F;          // [32][516]
    float* sG = sm + SW_F + SH_F;   // [32][33]

    int tid = threadIdx.x;
    int bx  = blockIdx.x;
    int h0  = (bx >> 1) * 8;
    int b0  = (bx & 1) * 32;

    // ---- load weight slice ONCE: sW[col][k] = W_g[k*HH + h0+hl], col=g*8+hl
    for (int v = tid; v < 32 * HH; v += 256) {
        int col = v & 31;
        int k   = v >> 5;
        int g   = col >> 3;
        int hl  = col & 7;
        const float* Wg = (g == 0) ? Wfh : (g == 1) ? Wih : (g == 2) ? Wgh : Woh;
        sW[col * 516 + k] = Wg[k * HH + h0 + hl];
    }

    // ---- zero h buffer 0 (one element per thread chip-wide: 128*256 = 32768)
    g_h[0][bx * 256 + tid] = 0.f;

    // compute-phase thread mapping: lane = column, warp picks 4 batches
    int lane = tid & 31;
    int warp = tid >> 5;
    int cg   = lane >> 3;     // gate of this column
    int chl  = lane & 7;      // h-local of this column
    const float* wp = sW + lane * 516;
    const float* hp0 = sh + (warp * 4 + 0) * 516;
    const float* hp1 = sh + (warp * 4 + 1) * 516;
    const float* hp2 = sh + (warp * 4 + 2) * 516;
    const float* hp3 = sh + (warp * 4 + 3) * 516;

    // pointwise-phase mapping: thread owns cell (b0+bl, h0+hl); c in register
    int bl = tid >> 3;
    int phl = tid & 7;
    float c_reg = 0.f;

    grid_barrier();   // h zero + W loads visible

    for (int t = 0; t < TT; t++) {
        const float* hsrc = g_h[t & 1];
        // ---- stage h_prev rows [b0, b0+32) x 512 into smem (bypass L1)
        for (int v = tid; v < 32 * 128; v += 256) {
            int row = v >> 7;
            int c4  = v & 127;
            float4 hv = __ldcg((const float4*)&hsrc[(b0 + row) * HH + c4 * 4]);
            *(float4*)&sh[row * 516 + c4 * 4] = hv;
        }

        // ---- init accumulators from pre-activations
        const float* pre_t = g_pre + (size_t)t * 4 * BB * HH;
        int bb = b0 + warp * 4;
        float acc0 = __ldg(&pre_t[((cg * 64) + bb + 0) * HH + h0 + chl]);
        float acc1 = __ldg(&pre_t[((cg * 64) + bb + 1) * HH + h0 + chl]);
        float acc2 = __ldg(&pre_t[((cg * 64) + bb + 2) * HH + h0 + chl]);
        float acc3 = __ldg(&pre_t[((cg * 64) + bb + 3) * HH + h0 + chl]);
        __syncthreads();

        // ---- gates GEMM: acc_j += dot(W[:,col], h[b_j,:])
        #pragma unroll 8
        for (int k = 0; k < HH; k += 4) {
            float4 w = *(const float4*)(wp + k);
            float4 a = *(const float4*)(hp0 + k);
            acc0 += w.x * a.x + w.y * a.y + w.z * a.z + w.w * a.w;
            float4 b = *(const float4*)(hp1 + k);
            acc1 += w.x * b.x + w.y * b.y + w.z * b.z + w.w * b.w;
            float4 c = *(const float4*)(hp2 + k);
            acc2 += w.x * c.x + w.y * c.y + w.z * c.z + w.w * c.w;
            float4 d = *(const float4*)(hp3 + k);
            acc3 += w.x * d.x + w.y * d.y + w.z * d.z + w.w * d.w;
        }

        // ---- publish gates to smem
        sG[(warp * 4 + 0) * 33 + lane] = acc0;
        sG[(warp * 4 + 1) * 33 + lane] = acc1;
        sG[(warp * 4 + 2) * 33 + lane] = acc2;
        sG[(warp * 4 + 3) * 33 + lane] = acc3;
        __syncthreads();

        // ---- pointwise cell update (c stays in register)
        float pf = sG[bl * 33 +  0 + phl];
        float pi = sG[bl * 33 +  8 + phl];
        float pg = sG[bl * 33 + 16 + phl];
        float po = sG[bl * 33 + 24 + phl];
        float f  = 1.f / (1.f + expf(-pf));
        float i  = 1.f / (1.f + expf(-pi));
        float g  = tanhf(pg);
        float o  = 1.f / (1.f + expf(-po));
        c_reg = f * c_reg + i * g;
        float hnew = o * tanhf(c_reg);
        __stcg(&g_h[(t + 1) & 1][(b0 + bl) * HH + h0 + phl], hnew);

        grid_barrier();
    }

    // ---- write final c (h_t already in g_h[0] since (255+1)&1 == 0)
    g_c[(b0 + bl) * HH + h0 + phl] = c_reg;
}

// ---------------- final: out = h @ W_lin + b_lin; emit (out, h, c) ----------
__global__ void final_k(const float* __restrict__ Wlin, const float* __restrict__ blin,
                        float* __restrict__ out) {
    int b = blockIdx.x;
    int tid = threadIdx.x;
    const float* h = g_h[0];
    const float* c = g_c;

    float* out_h = out + BB * OO;
    float* out_c = out + BB * OO + BB * HH;
    for (int v = tid; v < HH; v += 256) {
        out_h[b * HH + v] = h[b * HH + v];
        out_c[b * HH + v] = c[b * HH + v];
    }

    __shared__ float red[256 * OO];
    float p[OO];
    #pragma unroll
    for (int o = 0; o < OO; o++) p[o] = 0.f;
    for (int k = tid; k < HH; k += 256) {
        float hv = h[b * HH + k];
        #pragma unroll
        for (int o = 0; o < OO; o++) p[o] += hv * Wlin[k * OO + o];
    }
    #pragma unroll
    for (int o = 0; o < OO; o++) red[tid * OO + o] = p[o];
    __syncthreads();
    for (int s = 128; s > 0; s >>= 1) {
        if (tid < s)
            #pragma unroll
            for (int o = 0; o < OO; o++) red[tid * OO + o] += red[(tid + s) * OO + o];
        __syncthreads();
    }
    if (tid < OO) out[b * OO + tid] = red[tid] + blin[tid];
}

// ---------------- host launcher ---------------------------------------------
extern "C" void kernel_launch(void* const* d_in, const int* in_sizes, int n_in,
                              void* d_out, int out_size) {
    const int*   x    = (const int*)d_in[0];
    const float* emb  = (const float*)d_in[1];
    const float* Wfx  = (const float*)d_in[2];
    const float* Wfh  = (const float*)d_in[3];
    const float* bf   = (const float*)d_in[4];
    const float* Wix  = (const float*)d_in[5];
    const float* Wih  = (const float*)d_in[6];
    const float* bi   = (const float*)d_in[7];
    const float* Wgx  = (const float*)d_in[8];
    const float* Wgh  = (const float*)d_in[9];
    const float* bg   = (const float*)d_in[10];
    const float* Wox  = (const float*)d_in[11];
    const float* Woh  = (const float*)d_in[12];
    const float* bo   = (const float*)d_in[13];
    const float* Wlin = (const float*)d_in[14];
    const float* blin = (const float*)d_in[15];
    float* out = (float*)d_out;

    cudaFuncSetAttribute(lstm_persist, cudaFuncAttributeMaxDynamicSharedMemorySize,
                         SMEM_BYTES);

    gemm_pre<<<dim3(NN / Bb_N, MM / Bb_M), 256>>>(x, emb, Wfx, Wix, Wgx, Wox,
                                                  bf, bi, bg, bo);
    lstm_persist<<<NBLK, 256, SMEM_BYTES>>>(Wfh, Wih, Wgh, Woh);
    final_k<<<BB, 256>>>(Wlin, blin, out);
}

// round 7
// speedup vs baseline: 3.2374x; 2.4078x over previous
#include <cuda_runtime.h>
#include <cuda_bf16.h>
#include <math.h>
#include <stdint.h>

// Problem constants
#define BB 64
#define PP 16
#define TT 256
#define II 256
#define HH 512
#define OO 5
#define KK 4096      // P*I
#define MM 16384     // B*T
#define NT 2048      // 4*H

#define NBLK 128     // persistent recurrence grid

// ---------------- scratch (device globals) -----------------------------------
__device__ float g_pre[(size_t)TT * 4 * BB * HH];     // [t][gate][b][h]
__device__ __nv_bfloat16 g_Ah[(size_t)MM * KK];
__device__ __nv_bfloat16 g_Al[(size_t)MM * KK];
__device__ __nv_bfloat16 g_Bh[(size_t)NT * KK];       // [n][k]
__device__ __nv_bfloat16 g_Bl[(size_t)NT * KK];
__device__ float g_h[2][BB * HH];
__device__ float g_c[BB * HH];
__device__ unsigned g_count = 0;
__device__ unsigned g_gen = 0;

// ---------------- helpers ----------------------------------------------------
__device__ __forceinline__ uint32_t smem_u32(const void* p) {
    uint32_t a;
    asm("{ .reg .u64 t; cvta.to.shared.u64 t, %1; cvt.u32.u64 %0, t; }" : "=r"(a) : "l"(p));
    return a;
}
__device__ __forceinline__ void cp16(uint32_t dst, const void* src) {
    asm volatile("cp.async.cg.shared.global [%0], [%1], 16;" :: "r"(dst), "l"(src));
}
__device__ __forceinline__ void cp_commit() {
    asm volatile("cp.async.commit_group;" ::: "memory");
}
__device__ __forceinline__ void ldsm4(uint32_t* r, uint32_t addr) {
    asm volatile("ldmatrix.sync.aligned.m8n8.x4.shared.b16 {%0,%1,%2,%3}, [%4];"
                 : "=r"(r[0]), "=r"(r[1]), "=r"(r[2]), "=r"(r[3]) : "r"(addr));
}
__device__ __forceinline__ void mma_bf16(float* d, const uint32_t* a, const uint32_t* b) {
    asm volatile(
        "mma.sync.aligned.m16n8k16.row.col.f32.bf16.bf16.f32 "
        "{%0,%1,%2,%3}, {%4,%5,%6,%7}, {%8,%9}, {%0,%1,%2,%3};"
        : "+f"(d[0]), "+f"(d[1]), "+f"(d[2]), "+f"(d[3])
        : "r"(a[0]), "r"(a[1]), "r"(a[2]), "r"(a[3]), "r"(b[0]), "r"(b[1]));
}
#define SW128(o) ((o) ^ (((o) >> 3) & 0x70))

// ---------------- prep A: gather + split to bf16 hi/lo -----------------------
__global__ void prep_A(const int* __restrict__ x, const float* __restrict__ emb) {
    int v = blockIdx.x * 256 + threadIdx.x;   // 16.78M float4
    int m = v >> 10;
    int k = (v & 1023) << 2;
    int p = k >> 8, i = k & 255;
    int t = m >> 6, b = m & 63;
    int idx = x[(b * PP + p) * TT + t];
    float4 a = make_float4(0.f, 0.f, 0.f, 0.f);
    if (idx != 0) a = *(const float4*)&emb[(size_t)idx * II + i];
    __nv_bfloat16 h0 = __float2bfloat16(a.x);
    __nv_bfloat16 h1 = __float2bfloat16(a.y);
    __nv_bfloat16 h2 = __float2bfloat16(a.z);
    __nv_bfloat16 h3 = __float2bfloat16(a.w);
    __nv_bfloat16 l0 = __float2bfloat16(a.x - __bfloat162float(h0));
    __nv_bfloat16 l1 = __float2bfloat16(a.y - __bfloat162float(h1));
    __nv_bfloat16 l2 = __float2bfloat16(a.z - __bfloat162float(h2));
    __nv_bfloat16 l3 = __float2bfloat16(a.w - __bfloat162float(h3));
    size_t o = (size_t)m * KK + k;
    *(__nv_bfloat162*)(g_Ah + o)     = __nv_bfloat162(h0, h1);
    *(__nv_bfloat162*)(g_Ah + o + 2) = __nv_bfloat162(h2, h3);
    *(__nv_bfloat162*)(g_Al + o)     = __nv_bfloat162(l0, l1);
    *(__nv_bfloat162*)(g_Al + o + 2) = __nv_bfloat162(l2, l3);
}

// ---------------- prep B: transpose W[k][h] -> B[n][k], split ----------------
__global__ void prep_B(const float* __restrict__ Wf, const float* __restrict__ Wi,
                       const float* __restrict__ Wg, const float* __restrict__ Wo) {
    __shared__ float tile[32][33];
    int k0 = blockIdx.x * 32;
    int n0 = blockIdx.y * 32;
    int gate = n0 >> 9;
    int h0 = n0 & 511;
    const float* W = (gate == 0) ? Wf : (gate == 1) ? Wi : (gate == 2) ? Wg : Wo;
    int tx = threadIdx.x, ty = threadIdx.y;
    tile[ty][tx] = W[(size_t)(k0 + ty) * HH + h0 + tx];
    __syncthreads();
    float v = tile[tx][ty];
    __nv_bfloat16 hi = __float2bfloat16(v);
    __nv_bfloat16 lo = __float2bfloat16(v - __bfloat162float(hi));
    size_t o = (size_t)(n0 + ty) * KK + k0 + tx;
    g_Bh[o] = hi;
    g_Bl[o] = lo;
}

// ---------------- mma.sync GEMM: pre = A @ B^T + bias ------------------------
// CTA tile 128x128; K' = 3*4096 as 192 chunks of 64 (3-term bf16 split).
// 8 warps: warp_m = wid&3 (32 rows), warp_n = wid>>2 (64 cols).
#define KCH 64
#define ABUF 16384                   // 128 x 64 bf16
#define STAGE (2 * ABUF)             // A + B per stage
#define GEMM_SMEM (2 * STAGE)        // 65536, double buffered

__global__ void __launch_bounds__(256, 2)
mma_gemm(const float* __restrict__ bfp, const float* __restrict__ bip,
         const float* __restrict__ bgp, const float* __restrict__ bop) {
    extern __shared__ char smc[];
    uint32_t sbase = smem_u32(smc);
    int tid = threadIdx.x;
    int lane = tid & 31;
    int wid = tid >> 5;
    int mt = blockIdx.y;         // 0..127
    int nt = blockIdx.x;         // 0..15
    int warp_m = wid & 3;
    int warp_n = wid >> 2;

    size_t moff = (size_t)(mt * 128) * KK;
    size_t noff = (size_t)(nt * 128) * KK;
    const __nv_bfloat16* Asel[3] = { g_Ah + moff, g_Al + moff, g_Ah + moff };
    const __nv_bfloat16* Bsel[3] = { g_Bh + noff, g_Bh + noff, g_Bl + noff };

    float acc[2][8][4];
    #pragma unroll
    for (int mf = 0; mf < 2; mf++)
        #pragma unroll
        for (int nf = 0; nf < 8; nf++)
            #pragma unroll
            for (int e = 0; e < 4; e++) acc[mf][nf][e] = 0.f;

    // ---- stage chunk `it` into buffer it&1
    auto stage = [&](int it) {
        int phase = it >> 6, c = it & 63;
        const __nv_bfloat16* A = Asel[phase];
        const __nv_bfloat16* B = Bsel[phase];
        uint32_t ab = sbase + (uint32_t)(it & 1) * STAGE;
        uint32_t bb = ab + ABUF;
        #pragma unroll
        for (int i = 0; i < 4; i++) {
            int v = i * 256 + tid;
            int r = v >> 3, q = v & 7;
            uint32_t so = SW128(r * 128 + q * 16);
            cp16(ab + so, A + (size_t)r * KK + c * KCH + q * 8);
            cp16(bb + so, B + (size_t)r * KK + c * KCH + q * 8);
        }
        cp_commit();
    };

    stage(0);
    for (int it = 0; it < 192; it++) {
        if (it < 191) {
            stage(it + 1);
            asm volatile("cp.async.wait_group 1;" ::: "memory");
        } else {
            asm volatile("cp.async.wait_group 0;" ::: "memory");
        }
        __syncthreads();

        uint32_t aBase = sbase + (uint32_t)(it & 1) * STAGE;
        uint32_t bBase = aBase + ABUF;
        int arow = lane & 15, asel = lane >> 4;
        int bgrp = lane >> 3, brow = lane & 7;
        #pragma unroll
        for (int ks = 0; ks < 4; ks++) {
            uint32_t a[2][4];
            #pragma unroll
            for (int mf = 0; mf < 2; mf++) {
                int row = warp_m * 32 + mf * 16 + arow;
                ldsm4(a[mf], aBase + SW128(row * 128 + ks * 32 + asel * 16));
            }
            uint32_t b[4][4];
            #pragma unroll
            for (int nfp = 0; nfp < 4; nfp++) {
                int n = warp_n * 64 + nfp * 16 + ((bgrp >> 1) << 3) + brow;
                int kb = ks * 32 + ((bgrp & 1) << 4);
                ldsm4(b[nfp], bBase + SW128(n * 128 + kb));
            }
            #pragma unroll
            for (int mf = 0; mf < 2; mf++)
                #pragma unroll
                for (int nf = 0; nf < 8; nf++)
                    mma_bf16(acc[mf][nf], a[mf], &b[nf >> 1][(nf & 1) * 2]);
        }
        __syncthreads();
    }

    // ---- epilogue: + bias, scatter to g_pre[t][gate][b][h]
    int gate = nt >> 2;
    int hbase = (nt & 3) * 128;
    const float* bias = (gate == 0) ? bfp : (gate == 1) ? bip : (gate == 2) ? bgp : bop;
    int grp = lane >> 2, qd = lane & 3;
    #pragma unroll
    for (int mf = 0; mf < 2; mf++) {
        int mrow0 = mt * 128 + warp_m * 32 + mf * 16 + grp;
        #pragma unroll
        for (int half = 0; half < 2; half++) {
            int m = mrow0 + half * 8;
            int t = m >> 6, b = m & 63;
            float* dst = g_pre + ((size_t)(t * 4 + gate) * 64 + b) * 512 + hbase;
            #pragma unroll
            for (int nf = 0; nf < 8; nf++) {
                int col = warp_n * 64 + nf * 8 + qd * 2;
                float2 v;
                v.x = acc[mf][nf][half * 2 + 0] + __ldg(&bias[hbase + col]);
                v.y = acc[mf][nf][half * 2 + 1] + __ldg(&bias[hbase + col + 1]);
                *(float2*)(dst + col) = v;
            }
        }
    }
}

// ---------------- persistent LSTM recurrence ---------------------------------
#define SW_F (32 * 516)
#define SH_F (32 * 516)
#define SG_F (32 * 33)
#define LSTM_SMEM ((SW_F + SH_F + SG_F) * 4)

__device__ __forceinline__ void grid_barrier() {
    __threadfence();
    __syncthreads();
    if (threadIdx.x == 0) {
        unsigned gen = *((volatile unsigned*)&g_gen);
        if (atomicAdd(&g_count, 1u) == NBLK - 1) {
            g_count = 0;
            __threadfence();
            *((volatile unsigned*)&g_gen) = gen + 1;
        } else {
            while (*((volatile unsigned*)&g_gen) == gen) { }
        }
    }
    __syncthreads();
}

__global__ void __launch_bounds__(256, 1)
lstm_persist(const float* __restrict__ Wfh, const float* __restrict__ Wih,
             const float* __restrict__ Wgh, const float* __restrict__ Woh) {
    extern __shared__ float smf[];
    float* sW = smf;
    float* sh = smf + SW_F;
    float* sG = smf + SW_F + SH_F;

    int tid = threadIdx.x;
    int bx  = blockIdx.x;
    int h0  = (bx >> 1) * 8;
    int b0  = (bx & 1) * 32;

    for (int v = tid; v < 32 * HH; v += 256) {
        int col = v & 31;
        int k   = v >> 5;
        int g   = col >> 3;
        int hl  = col & 7;
        const float* Wg = (g == 0) ? Wfh : (g == 1) ? Wih : (g == 2) ? Wgh : Woh;
        sW[col * 516 + k] = Wg[k * HH + h0 + hl];
    }
    g_h[0][bx * 256 + tid] = 0.f;

    int lane = tid & 31;
    int warp = tid >> 5;
    int cg   = lane >> 3;
    int chl  = lane & 7;
    const float* wp = sW + lane * 516;
    const float* hp0 = sh + (warp * 4 + 0) * 516;
    const float* hp1 = sh + (warp * 4 + 1) * 516;
    const float* hp2 = sh + (warp * 4 + 2) * 516;
    const float* hp3 = sh + (warp * 4 + 3) * 516;

    int bl = tid >> 3;
    int phl = tid & 7;
    float c_reg = 0.f;

    grid_barrier();

    for (int t = 0; t < TT; t++) {
        const float* hsrc = g_h[t & 1];
        for (int v = tid; v < 32 * 128; v += 256) {
            int row = v >> 7;
            int c4  = v & 127;
            float4 hv = __ldcg((const float4*)&hsrc[(b0 + row) * HH + c4 * 4]);
            *(float4*)&sh[row * 516 + c4 * 4] = hv;
        }
        const float* pre_t = g_pre + (size_t)t * 4 * BB * HH;
        int bb = b0 + warp * 4;
        float acc0 = __ldg(&pre_t[((cg * 64) + bb + 0) * HH + h0 + chl]);
        float acc1 = __ldg(&pre_t[((cg * 64) + bb + 1) * HH + h0 + chl]);
        float acc2 = __ldg(&pre_t[((cg * 64) + bb + 2) * HH + h0 + chl]);
        float acc3 = __ldg(&pre_t[((cg * 64) + bb + 3) * HH + h0 + chl]);
        __syncthreads();

        #pragma unroll 8
        for (int k = 0; k < HH; k += 4) {
            float4 w = *(const float4*)(wp + k);
            float4 a = *(const float4*)(hp0 + k);
            acc0 += w.x * a.x + w.y * a.y + w.z * a.z + w.w * a.w;
            float4 b = *(const float4*)(hp1 + k);
            acc1 += w.x * b.x + w.y * b.y + w.z * b.z + w.w * b.w;
            float4 c = *(const float4*)(hp2 + k);
            acc2 += w.x * c.x + w.y * c.y + w.z * c.z + w.w * c.w;
            float4 d = *(const float4*)(hp3 + k);
            acc3 += w.x * d.x + w.y * d.y + w.z * d.z + w.w * d.w;
        }
        sG[(warp * 4 + 0) * 33 + lane] = acc0;
        sG[(warp * 4 + 1) * 33 + lane] = acc1;
        sG[(warp * 4 + 2) * 33 + lane] = acc2;
        sG[(warp * 4 + 3) * 33 + lane] = acc3;
        __syncthreads();

        float pf = sG[bl * 33 +  0 + phl];
        float pi = sG[bl * 33 +  8 + phl];
        float pg = sG[bl * 33 + 16 + phl];
        float po = sG[bl * 33 + 24 + phl];
        float f  = 1.f / (1.f + expf(-pf));
        float i  = 1.f / (1.f + expf(-pi));
        float g  = tanhf(pg);
        float o  = 1.f / (1.f + expf(-po));
        c_reg = f * c_reg + i * g;
        float hnew = o * tanhf(c_reg);
        __stcg(&g_h[(t + 1) & 1][(b0 + bl) * HH + h0 + phl], hnew);

        grid_barrier();
    }
    g_c[(b0 + bl) * HH + h0 + phl] = c_reg;
}

// ---------------- final: out = h @ W_lin + b_lin; emit (out, h, c) ----------
__global__ void final_k(const float* __restrict__ Wlin, const float* __restrict__ blin,
                        float* __restrict__ out) {
    int b = blockIdx.x;
    int tid = threadIdx.x;
    const float* h = g_h[0];
    const float* c = g_c;

    float* out_h = out + BB * OO;
    float* out_c = out + BB * OO + BB * HH;
    for (int v = tid; v < HH; v += 256) {
        out_h[b * HH + v] = h[b * HH + v];
        out_c[b * HH + v] = c[b * HH + v];
    }
    __shared__ float red[256 * OO];
    float p[OO];
    #pragma unroll
    for (int o = 0; o < OO; o++) p[o] = 0.f;
    for (int k = tid; k < HH; k += 256) {
        float hv = h[b * HH + k];
        #pragma unroll
        for (int o = 0; o < OO; o++) p[o] += hv * Wlin[k * OO + o];
    }
    #pragma unroll
    for (int o = 0; o < OO; o++) red[tid * OO + o] = p[o];
    __syncthreads();
    for (int s = 128; s > 0; s >>= 1) {
        if (tid < s)
            #pragma unroll
            for (int o = 0; o < OO; o++) red[tid * OO + o] += red[(tid + s) * OO + o];
        __syncthreads();
    }
    if (tid < OO) out[b * OO + tid] = red[tid] + blin[tid];
}

// ---------------- host launcher ---------------------------------------------
extern "C" void kernel_launch(void* const* d_in, const int* in_sizes, int n_in,
                              void* d_out, int out_size) {
    const int*   x    = (const int*)d_in[0];
    const float* emb  = (const float*)d_in[1];
    const float* Wfx  = (const float*)d_in[2];
    const float* Wfh  = (const float*)d_in[3];
    const float* bfp  = (const float*)d_in[4];
    const float* Wix  = (const float*)d_in[5];
    const float* Wih  = (const float*)d_in[6];
    const float* bip  = (const float*)d_in[7];
    const float* Wgx  = (const float*)d_in[8];
    const float* Wgh  = (const float*)d_in[9];
    const float* bgp  = (const float*)d_in[10];
    const float* Wox  = (const float*)d_in[11];
    const float* Woh  = (const float*)d_in[12];
    const float* bop  = (const float*)d_in[13];
    const float* Wlin = (const float*)d_in[14];
    const float* blin = (const float*)d_in[15];
    float* out = (float*)d_out;

    cudaFuncSetAttribute(mma_gemm, cudaFuncAttributeMaxDynamicSharedMemorySize, GEMM_SMEM);
    cudaFuncSetAttribute(lstm_persist, cudaFuncAttributeMaxDynamicSharedMemorySize, LSTM_SMEM);

    prep_A<<<65536, 256>>>(x, emb);
    prep_B<<<dim3(KK / 32, NT / 32), dim3(32, 32)>>>(Wfx, Wix, Wgx, Wox);
    mma_gemm<<<dim3(NT / 128, MM / 128), 256, GEMM_SMEM>>>(bfp, bip, bgp, bop);
    lstm_persist<<<NBLK, 256, LSTM_SMEM>>>(Wfh, Wih, Wgh, Woh);
    final_k<<<BB, 256>>>(Wlin, blin, out);
}

// round 8
// speedup vs baseline: 4.0528x; 1.2519x over previous
#include <cuda_runtime.h>
#include <cuda_bf16.h>
#include <math.h>
#include <stdint.h>

// Problem constants
#define BB 64
#define PP 16
#define TT 256
#define II 256
#define HH 512
#define OO 5
#define KK 4096      // P*I
#define MM 16384     // B*T
#define NT 2048      // 4*H

#define NBLK 128     // persistent recurrence grid

// ---------------- scratch (device globals) -----------------------------------
__device__ float g_pre[(size_t)TT * 4 * BB * HH];     // [t][gate][b][h]
__device__ __nv_bfloat16 g_Ah[(size_t)MM * KK];
__device__ __nv_bfloat16 g_Al[(size_t)MM * KK];
__device__ __nv_bfloat16 g_Bh[(size_t)NT * KK];       // [n][k]
__device__ __nv_bfloat16 g_Bl[(size_t)NT * KK];
__device__ __nv_bfloat16 g_Wcat[(size_t)NT * 1536];   // [h*4+gate][k'] recurrence W
__device__ float g_h[2][BB * HH];
__device__ float g_c[BB * HH];
__device__ unsigned g_count = 0;
__device__ unsigned g_gen = 0;

// ---------------- helpers ----------------------------------------------------
__device__ __forceinline__ uint32_t smem_u32(const void* p) {
    uint32_t a;
    asm("{ .reg .u64 t; cvta.to.shared.u64 t, %1; cvt.u32.u64 %0, t; }" : "=r"(a) : "l"(p));
    return a;
}
__device__ __forceinline__ void cp16(uint32_t dst, const void* src) {
    asm volatile("cp.async.cg.shared.global [%0], [%1], 16;" :: "r"(dst), "l"(src));
}
__device__ __forceinline__ void cp_commit() {
    asm volatile("cp.async.commit_group;" ::: "memory");
}
__device__ __forceinline__ void ldsm4(uint32_t* r, uint32_t addr) {
    asm volatile("ldmatrix.sync.aligned.m8n8.x4.shared.b16 {%0,%1,%2,%3}, [%4];"
                 : "=r"(r[0]), "=r"(r[1]), "=r"(r[2]), "=r"(r[3]) : "r"(addr));
}
__device__ __forceinline__ void ldsm2(uint32_t* r, uint32_t addr) {
    asm volatile("ldmatrix.sync.aligned.m8n8.x2.shared.b16 {%0,%1}, [%2];"
                 : "=r"(r[0]), "=r"(r[1]) : "r"(addr));
}
__device__ __forceinline__ void mma_bf16(float* d, const uint32_t* a, const uint32_t* b) {
    asm volatile(
        "mma.sync.aligned.m16n8k16.row.col.f32.bf16.bf16.f32 "
        "{%0,%1,%2,%3}, {%4,%5,%6,%7}, {%8,%9}, {%0,%1,%2,%3};"
        : "+f"(d[0]), "+f"(d[1]), "+f"(d[2]), "+f"(d[3])
        : "r"(a[0]), "r"(a[1]), "r"(a[2]), "r"(a[3]), "r"(b[0]), "r"(b[1]));
}
__device__ __forceinline__ uint32_t pack_bf16(float a, float b) {
    __nv_bfloat162 v(__float2bfloat16(a), __float2bfloat16(b));
    return *(uint32_t*)&v;
}
#define SW128(o) ((o) ^ (((o) >> 3) & 0x70))

// ---------------- prep A: gather + split to bf16 hi/lo -----------------------
__global__ void prep_A(const int* __restrict__ x, const float* __restrict__ emb) {
    int v = blockIdx.x * 256 + threadIdx.x;
    int m = v >> 10;
    int k = (v & 1023) << 2;
    int p = k >> 8, i = k & 255;
    int t = m >> 6, b = m & 63;
    int idx = x[(b * PP + p) * TT + t];
    float4 a = make_float4(0.f, 0.f, 0.f, 0.f);
    if (idx != 0) a = *(const float4*)&emb[(size_t)idx * II + i];
    __nv_bfloat16 h0 = __float2bfloat16(a.x);
    __nv_bfloat16 h1 = __float2bfloat16(a.y);
    __nv_bfloat16 h2 = __float2bfloat16(a.z);
    __nv_bfloat16 h3 = __float2bfloat16(a.w);
    __nv_bfloat16 l0 = __float2bfloat16(a.x - __bfloat162float(h0));
    __nv_bfloat16 l1 = __float2bfloat16(a.y - __bfloat162float(h1));
    __nv_bfloat16 l2 = __float2bfloat16(a.z - __bfloat162float(h2));
    __nv_bfloat16 l3 = __float2bfloat16(a.w - __bfloat162float(h3));
    size_t o = (size_t)m * KK + k;
    *(__nv_bfloat162*)(g_Ah + o)     = __nv_bfloat162(h0, h1);
    *(__nv_bfloat162*)(g_Ah + o + 2) = __nv_bfloat162(h2, h3);
    *(__nv_bfloat162*)(g_Al + o)     = __nv_bfloat162(l0, l1);
    *(__nv_bfloat162*)(g_Al + o + 2) = __nv_bfloat162(l2, l3);
}

// ---------------- prep B: transpose W[k][h] -> B[n][k], split ----------------
__global__ void prep_B(const float* __restrict__ Wf, const float* __restrict__ Wi,
                       const float* __restrict__ Wg, const float* __restrict__ Wo) {
    __shared__ float tile[32][33];
    int k0 = blockIdx.x * 32;
    int n0 = blockIdx.y * 32;
    int gate = n0 >> 9;
    int h0 = n0 & 511;
    const float* W = (gate == 0) ? Wf : (gate == 1) ? Wi : (gate == 2) ? Wg : Wo;
    int tx = threadIdx.x, ty = threadIdx.y;
    tile[ty][tx] = W[(size_t)(k0 + ty) * HH + h0 + tx];
    __syncthreads();
    float v = tile[tx][ty];
    __nv_bfloat16 hi = __float2bfloat16(v);
    __nv_bfloat16 lo = __float2bfloat16(v - __bfloat162float(hi));
    size_t o = (size_t)(n0 + ty) * KK + k0 + tx;
    g_Bh[o] = hi;
    g_Bl[o] = lo;
}

// ---------------- prep Wcat: recurrence weights, gate-interleaved, split -----
// Wcat[c][k'], c = h*4+gate, k' in [0,1536):
//   seg0 (k'<512):   bf16_hi(W_g[k'][h])     pairs with Hh
//   seg1 (<1024):    bf16_hi(W_g[k'-512][h]) pairs with Hl
//   seg2 (<1536):    bf16_lo(W_g[k'-1024][h]) pairs with Hh
__global__ void prep_Wcat(const float* __restrict__ Wf, const float* __restrict__ Wi,
                          const float* __restrict__ Wg, const float* __restrict__ Wo) {
    int c = blockIdx.x / 6;
    int kp = (blockIdx.x % 6) * 256 + threadIdx.x;   // 0..1535
    int g = c & 3;
    int h = c >> 2;
    int seg = kp >> 9;
    int kk = kp & 511;
    const float* W = (g == 0) ? Wf : (g == 1) ? Wi : (g == 2) ? Wg : Wo;
    float val = W[(size_t)kk * HH + h];
    __nv_bfloat16 hi = __float2bfloat16(val);
    __nv_bfloat16 out = (seg == 2) ? __float2bfloat16(val - __bfloat162float(hi)) : hi;
    g_Wcat[(size_t)c * 1536 + kp] = out;
}

// ---------------- mma.sync GEMM: pre = A @ B^T + bias ------------------------
#define KCH 64
#define ABUF 16384
#define STAGE (2 * ABUF)
#define GEMM_SMEM (2 * STAGE)

__global__ void __launch_bounds__(256, 2)
mma_gemm(const float* __restrict__ bfp, const float* __restrict__ bip,
         const float* __restrict__ bgp, const float* __restrict__ bop) {
    extern __shared__ char smc[];
    uint32_t sbase = smem_u32(smc);
    int tid = threadIdx.x;
    int lane = tid & 31;
    int wid = tid >> 5;
    int mt = blockIdx.y;
    int nt = blockIdx.x;
    int warp_m = wid & 3;
    int warp_n = wid >> 2;

    size_t moff = (size_t)(mt * 128) * KK;
    size_t noff = (size_t)(nt * 128) * KK;
    const __nv_bfloat16* Asel[3] = { g_Ah + moff, g_Al + moff, g_Ah + moff };
    const __nv_bfloat16* Bsel[3] = { g_Bh + noff, g_Bh + noff, g_Bl + noff };

    float acc[2][8][4];
    #pragma unroll
    for (int mf = 0; mf < 2; mf++)
        #pragma unroll
        for (int nf = 0; nf < 8; nf++)
            #pragma unroll
            for (int e = 0; e < 4; e++) acc[mf][nf][e] = 0.f;

    auto stage = [&](int it) {
        int phase = it >> 6, c = it & 63;
        const __nv_bfloat16* A = Asel[phase];
        const __nv_bfloat16* B = Bsel[phase];
        uint32_t ab = sbase + (uint32_t)(it & 1) * STAGE;
        uint32_t bb = ab + ABUF;
        #pragma unroll
        for (int i = 0; i < 4; i++) {
            int v = i * 256 + tid;
            int r = v >> 3, q = v & 7;
            uint32_t so = SW128(r * 128 + q * 16);
            cp16(ab + so, A + (size_t)r * KK + c * KCH + q * 8);
            cp16(bb + so, B + (size_t)r * KK + c * KCH + q * 8);
        }
        cp_commit();
    };

    stage(0);
    for (int it = 0; it < 192; it++) {
        if (it < 191) {
            stage(it + 1);
            asm volatile("cp.async.wait_group 1;" ::: "memory");
        } else {
            asm volatile("cp.async.wait_group 0;" ::: "memory");
        }
        __syncthreads();

        uint32_t aBase = sbase + (uint32_t)(it & 1) * STAGE;
        uint32_t bBase = aBase + ABUF;
        int arow = lane & 15, asel = lane >> 4;
        int bgrp = lane >> 3, brow = lane & 7;
        #pragma unroll
        for (int ks = 0; ks < 4; ks++) {
            uint32_t a[2][4];
            #pragma unroll
            for (int mf = 0; mf < 2; mf++) {
                int row = warp_m * 32 + mf * 16 + arow;
                ldsm4(a[mf], aBase + SW128(row * 128 + ks * 32 + asel * 16));
            }
            uint32_t b[4][4];
            #pragma unroll
            for (int nfp = 0; nfp < 4; nfp++) {
                int n = warp_n * 64 + nfp * 16 + ((bgrp >> 1) << 3) + brow;
                int kb = ks * 32 + ((bgrp & 1) << 4);
                ldsm4(b[nfp], bBase + SW128(n * 128 + kb));
            }
            #pragma unroll
            for (int mf = 0; mf < 2; mf++)
                #pragma unroll
                for (int nf = 0; nf < 8; nf++)
                    mma_bf16(acc[mf][nf], a[mf], &b[nf >> 1][(nf & 1) * 2]);
        }
        __syncthreads();
    }

    int gate = nt >> 2;
    int hbase = (nt & 3) * 128;
    const float* bias = (gate == 0) ? bfp : (gate == 1) ? bip : (gate == 2) ? bgp : bop;
    int grp = lane >> 2, qd = lane & 3;
    #pragma unroll
    for (int mf = 0; mf < 2; mf++) {
        int mrow0 = mt * 128 + warp_m * 32 + mf * 16 + grp;
        #pragma unroll
        for (int half = 0; half < 2; half++) {
            int m = mrow0 + half * 8;
            int t = m >> 6, b = m & 63;
            float* dst = g_pre + ((size_t)(t * 4 + gate) * 64 + b) * 512 + hbase;
            #pragma unroll
            for (int nf = 0; nf < 8; nf++) {
                int col = warp_n * 64 + nf * 8 + qd * 2;
                float2 v;
                v.x = acc[mf][nf][half * 2 + 0] + __ldg(&bias[hbase + col]);
                v.y = acc[mf][nf][half * 2 + 1] + __ldg(&bias[hbase + col + 1]);
                *(float2*)(dst + col) = v;
            }
        }
    }
}

// ---------------- persistent LSTM recurrence (tensor cores) ------------------
// 128 blocks: colgrp = bx>>1 (32 cols = 8 h x 4 gates), b-group = bx&1 (32 b).
// smem: W' [24 chunks][32 rows x 64 k] = 96KB (loaded once)
//       A' same layout = 96KB (per step: [Hh, Hl, Hh] split of h rows)
//       sG [32][33] fp32 gates exchange
#define RW0 0
#define RA0 98304
#define RG0 196608
#define LSTM_SMEM (196608 + 32 * 33 * 4)

__device__ __forceinline__ void grid_barrier() {
    __threadfence();
    __syncthreads();
    if (threadIdx.x == 0) {
        unsigned gen = *((volatile unsigned*)&g_gen);
        if (atomicAdd(&g_count, 1u) == NBLK - 1) {
            g_count = 0;
            __threadfence();
            *((volatile unsigned*)&g_gen) = gen + 1;
        } else {
            while (*((volatile unsigned*)&g_gen) == gen) { }
        }
    }
    __syncthreads();
}

__global__ void __launch_bounds__(256, 1)
lstm_persist() {
    extern __shared__ char smx[];
    uint32_t sb = smem_u32(smx);
    float* sG = (float*)(smx + RG0);

    int tid = threadIdx.x;
    int bx  = blockIdx.x;
    int lane = tid & 31;
    int wid  = tid >> 5;
    int colgrp = bx >> 1;            // 0..63
    int b0 = (bx & 1) * 32;
    int h0 = colgrp * 8;
    int c0 = colgrp * 32;            // global col base (c = h*4+gate)

    // ---- load W' slice once: 32 cols x 1536 bf16, chunked + swizzled
    for (int v = tid; v < 32 * 192; v += 256) {
        int r = v / 192;             // col row 0..31
        int g8 = v % 192;            // 8-k group
        uint4 w = *(const uint4*)(g_Wcat + (size_t)(c0 + r) * 1536 + g8 * 8);
        int chunk = g8 >> 3;
        uint32_t off = SW128(r * 128 + (g8 & 7) * 16);
        *(uint4*)(smx + RW0 + chunk * 4096 + off) = w;
    }

    // zero h buffer 0
    g_h[0][bx * 256 + tid] = 0.f;

    // mma mapping: 8 warps, warp tile 16x8
    int mhalf = wid & 1;             // m rows 0-15 / 16-31
    int nq = wid >> 1;               // 8-col group 0..3
    // activation mapping: one cell per thread
    int bl = tid >> 3;               // 0..31
    int phl = tid & 7;               // 0..7
    float c_reg = 0.f;

    grid_barrier();

    for (int t = 0; t < TT; t++) {
        const float* hsrc = g_h[t & 1];
        // ---- stage A' = [Hh, Hl, Hh] (32 rows x 512 k fp32 -> bf16 split)
        for (int v = tid; v < 2048; v += 256) {
            int r = v >> 6;          // 0..31
            int grp = v & 63;        // 8-k group
            int k = grp * 8;
            float4 x0 = __ldcg((const float4*)&hsrc[(b0 + r) * HH + k]);
            float4 x1 = __ldcg((const float4*)&hsrc[(b0 + r) * HH + k + 4]);
            uint4 HI, LO;
            HI.x = pack_bf16(x0.x, x0.y); HI.y = pack_bf16(x0.z, x0.w);
            HI.z = pack_bf16(x1.x, x1.y); HI.w = pack_bf16(x1.z, x1.w);
            __nv_bfloat162 h01 = *(__nv_bfloat162*)&HI.x;
            __nv_bfloat162 h23 = *(__nv_bfloat162*)&HI.y;
            __nv_bfloat162 h45 = *(__nv_bfloat162*)&HI.z;
            __nv_bfloat162 h67 = *(__nv_bfloat162*)&HI.w;
            LO.x = pack_bf16(x0.x - __bfloat162float(h01.x), x0.y - __bfloat162float(h01.y));
            LO.y = pack_bf16(x0.z - __bfloat162float(h23.x), x0.w - __bfloat162float(h23.y));
            LO.z = pack_bf16(x1.x - __bfloat162float(h45.x), x1.y - __bfloat162float(h45.y));
            LO.w = pack_bf16(x1.z - __bfloat162float(h67.x), x1.w - __bfloat162float(h67.y));
            int chunk = grp >> 3;
            uint32_t off = SW128(r * 128 + (grp & 7) * 16);
            *(uint4*)(smx + RA0 + chunk * 4096 + off) = HI;         // seg0: Hh
            *(uint4*)(smx + RA0 + (chunk + 8) * 4096 + off) = LO;   // seg1: Hl
            *(uint4*)(smx + RA0 + (chunk + 16) * 4096 + off) = HI;  // seg2: Hh
        }
        // ---- prefetch pre[t] for this thread's cell (hidden under mma)
        const float* pre_t = g_pre + (size_t)t * 4 * BB * HH;
        float pf = __ldcg(&pre_t[((0 * 64) + b0 + bl) * HH + h0 + phl]);
        float pi = __ldcg(&pre_t[((1 * 64) + b0 + bl) * HH + h0 + phl]);
        float pg = __ldcg(&pre_t[((2 * 64) + b0 + bl) * HH + h0 + phl]);
        float po = __ldcg(&pre_t[((3 * 64) + b0 + bl) * HH + h0 + phl]);
        __syncthreads();

        // ---- gates mma: 16x8 warp tile over K' = 1536
        float acc[4] = {0.f, 0.f, 0.f, 0.f};
        int arow = mhalf * 16 + (lane & 15);
        int asel = lane >> 4;
        int ln = lane & 15;
        int brow = nq * 8 + (ln & 7);
        int bsel = (ln >> 3) & 1;
        #pragma unroll 4
        for (int kk16 = 0; kk16 < 96; kk16++) {
            int chunk = kk16 >> 2;
            int kb = (kk16 & 3) * 32;
            uint32_t a[4], b2[2];
            ldsm4(a, sb + RA0 + chunk * 4096 + SW128(arow * 128 + kb + asel * 16));
            ldsm2(b2, sb + RW0 + chunk * 4096 + SW128(brow * 128 + kb + bsel * 16));
            mma_bf16(acc, a, b2);
        }
        // ---- publish gates
        int rw = mhalf * 16 + (lane >> 2);
        int cw = nq * 8 + (lane & 3) * 2;
        sG[rw * 33 + cw]           = acc[0];
        sG[rw * 33 + cw + 1]       = acc[1];
        sG[(rw + 8) * 33 + cw]     = acc[2];
        sG[(rw + 8) * 33 + cw + 1] = acc[3];
        __syncthreads();

        // ---- cell update (c in register)
        float gf = pf + sG[bl * 33 + phl * 4 + 0];
        float gi = pi + sG[bl * 33 + phl * 4 + 1];
        float gg = pg + sG[bl * 33 + phl * 4 + 2];
        float go = po + sG[bl * 33 + phl * 4 + 3];
        float f  = 1.f / (1.f + expf(-gf));
        float i  = 1.f / (1.f + expf(-gi));
        float g  = tanhf(gg);
        float o  = 1.f / (1.f + expf(-go));
        c_reg = f * c_reg + i * g;
        float hnew = o * tanhf(c_reg);
        __stcg(&g_h[(t + 1) & 1][(b0 + bl) * HH + h0 + phl], hnew);

        grid_barrier();
    }
    g_c[(b0 + bl) * HH + h0 + phl] = c_reg;
}

// ---------------- final: out = h @ W_lin + b_lin; emit (out, h, c) ----------
__global__ void final_k(const float* __restrict__ Wlin, const float* __restrict__ blin,
                        float* __restrict__ out) {
    int b = blockIdx.x;
    int tid = threadIdx.x;
    const float* h = g_h[0];
    const float* c = g_c;

    float* out_h = out + BB * OO;
    float* out_c = out + BB * OO + BB * HH;
    for (int v = tid; v < HH; v += 256) {
        out_h[b * HH + v] = h[b * HH + v];
        out_c[b * HH + v] = c[b * HH + v];
    }
    __shared__ float red[256 * OO];
    float p[OO];
    #pragma unroll
    for (int o = 0; o < OO; o++) p[o] = 0.f;
    for (int k = tid; k < HH; k += 256) {
        float hv = h[b * HH + k];
        #pragma unroll
        for (int o = 0; o < OO; o++) p[o] += hv * Wlin[k * OO + o];
    }
    #pragma unroll
    for (int o = 0; o < OO; o++) red[tid * OO + o] = p[o];
    __syncthreads();
    for (int s = 128; s > 0; s >>= 1) {
        if (tid < s)
            #pragma unroll
            for (int o = 0; o < OO; o++) red[tid * OO + o] += red[(tid + s) * OO + o];
        __syncthreads();
    }
    if (tid < OO) out[b * OO + tid] = red[tid] + blin[tid];
}

// ---------------- host launcher ---------------------------------------------
extern "C" void kernel_launch(void* const* d_in, const int* in_sizes, int n_in,
                              void* d_out, int out_size) {
    const int*   x    = (const int*)d_in[0];
    const float* emb  = (const float*)d_in[1];
    const float* Wfx  = (const float*)d_in[2];
    const float* Wfh  = (const float*)d_in[3];
    const float* bfp  = (const float*)d_in[4];
    const float* Wix  = (const float*)d_in[5];
    const float* Wih  = (const float*)d_in[6];
    const float* bip  = (const float*)d_in[7];
    const float* Wgx  = (const float*)d_in[8];
    const float* Wgh  = (const float*)d_in[9];
    const float* bgp  = (const float*)d_in[10];
    const float* Wox  = (const float*)d_in[11];
    const float* Woh  = (const float*)d_in[12];
    const float* bop  = (const float*)d_in[13];
    const float* Wlin = (const float*)d_in[14];
    const float* blin = (const float*)d_in[15];
    float* out = (float*)d_out;

    cudaFuncSetAttribute(mma_gemm, cudaFuncAttributeMaxDynamicSharedMemorySize, GEMM_SMEM);
    cudaFuncSetAttribute(lstm_persist, cudaFuncAttributeMaxDynamicSharedMemorySize, LSTM_SMEM);

    prep_A<<<65536, 256>>>(x, emb);
    prep_B<<<dim3(KK / 32, NT / 32), dim3(32, 32)>>>(Wfx, Wix, Wgx, Wox);
    prep_Wcat<<<NT * 6, 256>>>(Wfh, Wih, Wgh, Woh);
    mma_gemm<<<dim3(NT / 128, MM / 128), 256, GEMM_SMEM>>>(bfp, bip, bgp, bop);
    lstm_persist<<<NBLK, 256, LSTM_SMEM>>>();
    final_k<<<BB, 256>>>(Wlin, blin, out);
}

// round 9
// speedup vs baseline: 4.8256x; 1.1907x over previous
#include <cuda_runtime.h>
#include <cuda_bf16.h>
#include <cuda_fp16.h>
#include <math.h>
#include <stdint.h>

// Problem constants
#define BB 64
#define PP 16
#define TT 256
#define II 256
#define HH 512
#define OO 5
#define KK 4096      // P*I
#define MM 16384     // B*T
#define NT 2048      // 4*H

#define NBLK 128     // persistent recurrence grid

// ---------------- scratch (device globals) -----------------------------------
__device__ float g_pre[(size_t)TT * 4 * BB * HH];     // [t][gate][b][h]
__device__ __half g_Ah[(size_t)MM * KK];              // fp16 hi of gathered A
__device__ __half g_Al[(size_t)MM * KK];              // fp16 lo of gathered A
__device__ __half g_Bh[(size_t)NT * KK];              // [n][k] fp16 hi of W_x
__device__ __nv_bfloat16 g_Wcat[(size_t)NT * 1536];   // [h*4+gate][k'] recurrence W (bf16 3-term)
__device__ float g_h[2][BB * HH];
__device__ float g_c[BB * HH];
__device__ unsigned g_count = 0;
__device__ unsigned g_gen = 0;

// ---------------- helpers ----------------------------------------------------
__device__ __forceinline__ uint32_t smem_u32(const void* p) {
    uint32_t a;
    asm("{ .reg .u64 t; cvta.to.shared.u64 t, %1; cvt.u32.u64 %0, t; }" : "=r"(a) : "l"(p));
    return a;
}
__device__ __forceinline__ void cp16(uint32_t dst, const void* src) {
    asm volatile("cp.async.cg.shared.global [%0], [%1], 16;" :: "r"(dst), "l"(src));
}
__device__ __forceinline__ void cp_commit() {
    asm volatile("cp.async.commit_group;" ::: "memory");
}
__device__ __forceinline__ void ldsm4(uint32_t* r, uint32_t addr) {
    asm volatile("ldmatrix.sync.aligned.m8n8.x4.shared.b16 {%0,%1,%2,%3}, [%4];"
                 : "=r"(r[0]), "=r"(r[1]), "=r"(r[2]), "=r"(r[3]) : "r"(addr));
}
__device__ __forceinline__ void ldsm2(uint32_t* r, uint32_t addr) {
    asm volatile("ldmatrix.sync.aligned.m8n8.x2.shared.b16 {%0,%1}, [%2];"
                 : "=r"(r[0]), "=r"(r[1]) : "r"(addr));
}
__device__ __forceinline__ void mma_bf16(float* d, const uint32_t* a, const uint32_t* b) {
    asm volatile(
        "mma.sync.aligned.m16n8k16.row.col.f32.bf16.bf16.f32 "
        "{%0,%1,%2,%3}, {%4,%5,%6,%7}, {%8,%9}, {%0,%1,%2,%3};"
        : "+f"(d[0]), "+f"(d[1]), "+f"(d[2]), "+f"(d[3])
        : "r"(a[0]), "r"(a[1]), "r"(a[2]), "r"(a[3]), "r"(b[0]), "r"(b[1]));
}
__device__ __forceinline__ void mma_f16(float* d, const uint32_t* a, const uint32_t* b) {
    asm volatile(
        "mma.sync.aligned.m16n8k16.row.col.f32.f16.f16.f32 "
        "{%0,%1,%2,%3}, {%4,%5,%6,%7}, {%8,%9}, {%0,%1,%2,%3};"
        : "+f"(d[0]), "+f"(d[1]), "+f"(d[2]), "+f"(d[3])
        : "r"(a[0]), "r"(a[1]), "r"(a[2]), "r"(a[3]), "r"(b[0]), "r"(b[1]));
}
__device__ __forceinline__ uint32_t pack_bf16(float a, float b) {
    __nv_bfloat162 v(__float2bfloat16(a), __float2bfloat16(b));
    return *(uint32_t*)&v;
}
#define SW128(o) ((o) ^ (((o) >> 3) & 0x70))

// ---------------- prep A: gather + fp16 hi/lo split --------------------------
__global__ void prep_A(const int* __restrict__ x, const float* __restrict__ emb) {
    int v = blockIdx.x * 256 + threadIdx.x;
    int m = v >> 10;
    int k = (v & 1023) << 2;
    int p = k >> 8, i = k & 255;
    int t = m >> 6, b = m & 63;
    int idx = x[(b * PP + p) * TT + t];
    float4 a = make_float4(0.f, 0.f, 0.f, 0.f);
    if (idx != 0) a = *(const float4*)&emb[(size_t)idx * II + i];
    __half h0 = __float2half(a.x);
    __half h1 = __float2half(a.y);
    __half h2 = __float2half(a.z);
    __half h3 = __float2half(a.w);
    __half l0 = __float2half(a.x - __half2float(h0));
    __half l1 = __float2half(a.y - __half2float(h1));
    __half l2 = __float2half(a.z - __half2float(h2));
    __half l3 = __float2half(a.w - __half2float(h3));
    size_t o = (size_t)m * KK + k;
    *(__half2*)(g_Ah + o)     = __half2(h0, h1);
    *(__half2*)(g_Ah + o + 2) = __half2(h2, h3);
    *(__half2*)(g_Al + o)     = __half2(l0, l1);
    *(__half2*)(g_Al + o + 2) = __half2(l2, l3);
}

// ---------------- prep B: transpose W[k][h] -> B[n][k], fp16 hi only ---------
__global__ void prep_B(const float* __restrict__ Wf, const float* __restrict__ Wi,
                       const float* __restrict__ Wg, const float* __restrict__ Wo) {
    __shared__ float tile[32][33];
    int k0 = blockIdx.x * 32;
    int n0 = blockIdx.y * 32;
    int gate = n0 >> 9;
    int h0 = n0 & 511;
    const float* W = (gate == 0) ? Wf : (gate == 1) ? Wi : (gate == 2) ? Wg : Wo;
    int tx = threadIdx.x, ty = threadIdx.y;
    tile[ty][tx] = W[(size_t)(k0 + ty) * HH + h0 + tx];
    __syncthreads();
    float v = tile[tx][ty];
    g_Bh[(size_t)(n0 + ty) * KK + k0 + tx] = __float2half(v);
}

// ---------------- prep Wcat: recurrence weights (bf16 3-term, unchanged) -----
__global__ void prep_Wcat(const float* __restrict__ Wf, const float* __restrict__ Wi,
                          const float* __restrict__ Wg, const float* __restrict__ Wo) {
    int c = blockIdx.x / 6;
    int kp = (blockIdx.x % 6) * 256 + threadIdx.x;   // 0..1535
    int g = c & 3;
    int h = c >> 2;
    int seg = kp >> 9;
    int kk = kp & 511;
    const float* W = (g == 0) ? Wf : (g == 1) ? Wi : (g == 2) ? Wg : Wo;
    float val = W[(size_t)kk * HH + h];
    __nv_bfloat16 hi = __float2bfloat16(val);
    __nv_bfloat16 out = (seg == 2) ? __float2bfloat16(val - __bfloat162float(hi)) : hi;
    g_Wcat[(size_t)c * 1536 + kp] = out;
}

// ---------------- mma.sync GEMM: pre = A @ B^T + bias ------------------------
// 2-term fp16 split: K' = 2*4096 as 128 chunks of 64 ({Ah.Bh, Al.Bh}).
#define KCH 64
#define ABUF 16384
#define STAGE (2 * ABUF)
#define GEMM_SMEM (2 * STAGE)

__global__ void __launch_bounds__(256, 2)
mma_gemm(const float* __restrict__ bfp, const float* __restrict__ bip,
         const float* __restrict__ bgp, const float* __restrict__ bop) {
    extern __shared__ char smc[];
    uint32_t sbase = smem_u32(smc);
    int tid = threadIdx.x;
    int lane = tid & 31;
    int wid = tid >> 5;
    int mt = blockIdx.y;
    int nt = blockIdx.x;
    int warp_m = wid & 3;
    int warp_n = wid >> 2;

    size_t moff = (size_t)(mt * 128) * KK;
    size_t noff = (size_t)(nt * 128) * KK;
    const __half* Asel[2] = { g_Ah + moff, g_Al + moff };

    float acc[2][8][4];
    #pragma unroll
    for (int mf = 0; mf < 2; mf++)
        #pragma unroll
        for (int nf = 0; nf < 8; nf++)
            #pragma unroll
            for (int e = 0; e < 4; e++) acc[mf][nf][e] = 0.f;

    auto stage = [&](int it) {
        int phase = it >> 6, c = it & 63;
        const __half* A = Asel[phase];
        const __half* B = g_Bh + noff;
        uint32_t ab = sbase + (uint32_t)(it & 1) * STAGE;
        uint32_t bb = ab + ABUF;
        #pragma unroll
        for (int i = 0; i < 4; i++) {
            int v = i * 256 + tid;
            int r = v >> 3, q = v & 7;
            uint32_t so = SW128(r * 128 + q * 16);
            cp16(ab + so, A + (size_t)r * KK + c * KCH + q * 8);
            cp16(bb + so, B + (size_t)r * KK + c * KCH + q * 8);
        }
        cp_commit();
    };

    stage(0);
    for (int it = 0; it < 128; it++) {
        if (it < 127) {
            stage(it + 1);
            asm volatile("cp.async.wait_group 1;" ::: "memory");
        } else {
            asm volatile("cp.async.wait_group 0;" ::: "memory");
        }
        __syncthreads();

        uint32_t aBase = sbase + (uint32_t)(it & 1) * STAGE;
        uint32_t bBase = aBase + ABUF;
        int arow = lane & 15, asel = lane >> 4;
        int bgrp = lane >> 3, brow = lane & 7;
        #pragma unroll
        for (int ks = 0; ks < 4; ks++) {
            uint32_t a[2][4];
            #pragma unroll
            for (int mf = 0; mf < 2; mf++) {
                int row = warp_m * 32 + mf * 16 + arow;
                ldsm4(a[mf], aBase + SW128(row * 128 + ks * 32 + asel * 16));
            }
            uint32_t b[4][4];
            #pragma unroll
            for (int nfp = 0; nfp < 4; nfp++) {
                int n = warp_n * 64 + nfp * 16 + ((bgrp >> 1) << 3) + brow;
                int kb = ks * 32 + ((bgrp & 1) << 4);
                ldsm4(b[nfp], bBase + SW128(n * 128 + kb));
            }
            #pragma unroll
            for (int mf = 0; mf < 2; mf++)
                #pragma unroll
                for (int nf = 0; nf < 8; nf++)
                    mma_f16(acc[mf][nf], a[mf], &b[nf >> 1][(nf & 1) * 2]);
        }
        __syncthreads();
    }

    int gate = nt >> 2;
    int hbase = (nt & 3) * 128;
    const float* bias = (gate == 0) ? bfp : (gate == 1) ? bip : (gate == 2) ? bgp : bop;
    int grp = lane >> 2, qd = lane & 3;
    #pragma unroll
    for (int mf = 0; mf < 2; mf++) {
        int mrow0 = mt * 128 + warp_m * 32 + mf * 16 + grp;
        #pragma unroll
        for (int half = 0; half < 2; half++) {
            int m = mrow0 + half * 8;
            int t = m >> 6, b = m & 63;
            float* dst = g_pre + ((size_t)(t * 4 + gate) * 64 + b) * 512 + hbase;
            #pragma unroll
            for (int nf = 0; nf < 8; nf++) {
                int col = warp_n * 64 + nf * 8 + qd * 2;
                float2 v;
                v.x = acc[mf][nf][half * 2 + 0] + __ldg(&bias[hbase + col]);
                v.y = acc[mf][nf][half * 2 + 1] + __ldg(&bias[hbase + col + 1]);
                *(float2*)(dst + col) = v;
            }
        }
    }
}

// ---------------- persistent LSTM recurrence (tensor cores, bf16 3-term) -----
#define RW0 0
#define RA0 98304
#define RG0 196608
#define LSTM_SMEM (196608 + 32 * 33 * 4)

__device__ __forceinline__ void grid_barrier() {
    __threadfence();
    __syncthreads();
    if (threadIdx.x == 0) {
        unsigned gen = *((volatile unsigned*)&g_gen);
        if (atomicAdd(&g_count, 1u) == NBLK - 1) {
            g_count = 0;
            __threadfence();
            *((volatile unsigned*)&g_gen) = gen + 1;
        } else {
            while (*((volatile unsigned*)&g_gen) == gen) { }
        }
    }
    __syncthreads();
}

__global__ void __launch_bounds__(256, 1)
lstm_persist() {
    extern __shared__ char smx[];
    uint32_t sb = smem_u32(smx);
    float* sG = (float*)(smx + RG0);

    int tid = threadIdx.x;
    int bx  = blockIdx.x;
    int lane = tid & 31;
    int wid  = tid >> 5;
    int colgrp = bx >> 1;            // 0..63
    int b0 = (bx & 1) * 32;
    int h0 = colgrp * 8;
    int c0 = colgrp * 32;            // global col base (c = h*4+gate)

    // ---- load W' slice once: 32 cols x 1536 bf16, chunked + swizzled
    for (int v = tid; v < 32 * 192; v += 256) {
        int r = v / 192;
        int g8 = v % 192;
        uint4 w = *(const uint4*)(g_Wcat + (size_t)(c0 + r) * 1536 + g8 * 8);
        int chunk = g8 >> 3;
        uint32_t off = SW128(r * 128 + (g8 & 7) * 16);
        *(uint4*)(smx + RW0 + chunk * 4096 + off) = w;
    }

    g_h[0][bx * 256 + tid] = 0.f;

    int mhalf = wid & 1;
    int nq = wid >> 1;
    int bl = tid >> 3;
    int phl = tid & 7;
    float c_reg = 0.f;

    grid_barrier();

    for (int t = 0; t < TT; t++) {
        const float* hsrc = g_h[t & 1];
        for (int v = tid; v < 2048; v += 256) {
            int r = v >> 6;
            int grp = v & 63;
            int k = grp * 8;
            float4 x0 = __ldcg((const float4*)&hsrc[(b0 + r) * HH + k]);
            float4 x1 = __ldcg((const float4*)&hsrc[(b0 + r) * HH + k + 4]);
            uint4 HI, LO;
            HI.x = pack_bf16(x0.x, x0.y); HI.y = pack_bf16(x0.z, x0.w);
            HI.z = pack_bf16(x1.x, x1.y); HI.w = pack_bf16(x1.z, x1.w);
            __nv_bfloat162 h01 = *(__nv_bfloat162*)&HI.x;
            __nv_bfloat162 h23 = *(__nv_bfloat162*)&HI.y;
            __nv_bfloat162 h45 = *(__nv_bfloat162*)&HI.z;
            __nv_bfloat162 h67 = *(__nv_bfloat162*)&HI.w;
            LO.x = pack_bf16(x0.x - __bfloat162float(h01.x), x0.y - __bfloat162float(h01.y));
            LO.y = pack_bf16(x0.z - __bfloat162float(h23.x), x0.w - __bfloat162float(h23.y));
            LO.z = pack_bf16(x1.x - __bfloat162float(h45.x), x1.y - __bfloat162float(h45.y));
            LO.w = pack_bf16(x1.z - __bfloat162float(h67.x), x1.w - __bfloat162float(h67.y));
            int chunk = grp >> 3;
            uint32_t off = SW128(r * 128 + (grp & 7) * 16);
            *(uint4*)(smx + RA0 + chunk * 4096 + off) = HI;
            *(uint4*)(smx + RA0 + (chunk + 8) * 4096 + off) = LO;
            *(uint4*)(smx + RA0 + (chunk + 16) * 4096 + off) = HI;
        }
        const float* pre_t = g_pre + (size_t)t * 4 * BB * HH;
        float pf = __ldcg(&pre_t[((0 * 64) + b0 + bl) * HH + h0 + phl]);
        float pi = __ldcg(&pre_t[((1 * 64) + b0 + bl) * HH + h0 + phl]);
        float pg = __ldcg(&pre_t[((2 * 64) + b0 + bl) * HH + h0 + phl]);
        float po = __ldcg(&pre_t[((3 * 64) + b0 + bl) * HH + h0 + phl]);
        __syncthreads();

        float acc[4] = {0.f, 0.f, 0.f, 0.f};
        int arow = mhalf * 16 + (lane & 15);
        int asel = lane >> 4;
        int ln = lane & 15;
        int brow = nq * 8 + (ln & 7);
        int bsel = (ln >> 3) & 1;
        #pragma unroll 4
        for (int kk16 = 0; kk16 < 96; kk16++) {
            int chunk = kk16 >> 2;
            int kb = (kk16 & 3) * 32;
            uint32_t a[4], b2[2];
            ldsm4(a, sb + RA0 + chunk * 4096 + SW128(arow * 128 + kb + asel * 16));
            ldsm2(b2, sb + RW0 + chunk * 4096 + SW128(brow * 128 + kb + bsel * 16));
            mma_bf16(acc, a, b2);
        }
        int rw = mhalf * 16 + (lane >> 2);
        int cw = nq * 8 + (lane & 3) * 2;
        sG[rw * 33 + cw]           = acc[0];
        sG[rw * 33 + cw + 1]       = acc[1];
        sG[(rw + 8) * 33 + cw]     = acc[2];
        sG[(rw + 8) * 33 + cw + 1] = acc[3];
        __syncthreads();

        float gf = pf + sG[bl * 33 + phl * 4 + 0];
        float gi = pi + sG[bl * 33 + phl * 4 + 1];
        float gg = pg + sG[bl * 33 + phl * 4 + 2];
        float go = po + sG[bl * 33 + phl * 4 + 3];
        float f  = 1.f / (1.f + expf(-gf));
        float i  = 1.f / (1.f + expf(-gi));
        float g  = tanhf(gg);
        float o  = 1.f / (1.f + expf(-go));
        c_reg = f * c_reg + i * g;
        float hnew = o * tanhf(c_reg);
        __stcg(&g_h[(t + 1) & 1][(b0 + bl) * HH + h0 + phl], hnew);

        grid_barrier();
    }
    g_c[(b0 + bl) * HH + h0 + phl] = c_reg;
}

// ---------------- final: out = h @ W_lin + b_lin; emit (out, h, c) ----------
__global__ void final_k(const float* __restrict__ Wlin, const float* __restrict__ blin,
                        float* __restrict__ out) {
    int b = blockIdx.x;
    int tid = threadIdx.x;
    const float* h = g_h[0];
    const float* c = g_c;

    float* out_h = out + BB * OO;
    float* out_c = out + BB * OO + BB * HH;
    for (int v = tid; v < HH; v += 256) {
        out_h[b * HH + v] = h[b * HH + v];
        out_c[b * HH + v] = c[b * HH + v];
    }
    __shared__ float red[256 * OO];
    float p[OO];
    #pragma unroll
    for (int o = 0; o < OO; o++) p[o] = 0.f;
    for (int k = tid; k < HH; k += 256) {
        float hv = h[b * HH + k];
        #pragma unroll
        for (int o = 0; o < OO; o++) p[o] += hv * Wlin[k * OO + o];
    }
    #pragma unroll
    for (int o = 0; o < OO; o++) red[tid * OO + o] = p[o];
    __syncthreads();
    for (int s = 128; s > 0; s >>= 1) {
        if (tid < s)
            #pragma unroll
            for (int o = 0; o < OO; o++) red[tid * OO + o] += red[(tid + s) * OO + o];
        __syncthreads();
    }
    if (tid < OO) out[b * OO + tid] = red[tid] + blin[tid];
}

// ---------------- host launcher ---------------------------------------------
extern "C" void kernel_launch(void* const* d_in, const int* in_sizes, int n_in,
                              void* d_out, int out_size) {
    const int*   x    = (const int*)d_in[0];
    const float* emb  = (const float*)d_in[1];
    const float* Wfx  = (const float*)d_in[2];
    const float* Wfh  = (const float*)d_in[3];
    const float* bfp  = (const float*)d_in[4];
    const float* Wix  = (const float*)d_in[5];
    const float* Wih  = (const float*)d_in[6];
    const float* bip  = (const float*)d_in[7];
    const float* Wgx  = (const float*)d_in[8];
    const float* Wgh  = (const float*)d_in[9];
    const float* bgp  = (const float*)d_in[10];
    const float* Wox  = (const float*)d_in[11];
    const float* Woh  = (const float*)d_in[12];
    const float* bop  = (const float*)d_in[13];
    const float* Wlin = (const float*)d_in[14];
    const float* blin = (const float*)d_in[15];
    float* out = (float*)d_out;

    cudaFuncSetAttribute(mma_gemm, cudaFuncAttributeMaxDynamicSharedMemorySize, GEMM_SMEM);
    cudaFuncSetAttribute(lstm_persist, cudaFuncAttributeMaxDynamicSharedMemorySize, LSTM_SMEM);

    prep_A<<<65536, 256>>>(x, emb);
    prep_B<<<dim3(KK / 32, NT / 32), dim3(32, 32)>>>(Wfx, Wix, Wgx, Wox);
    prep_Wcat<<<NT * 6, 256>>>(Wfh, Wih, Wgh, Woh);
    mma_gemm<<<dim3(NT / 128, MM / 128), 256, GEMM_SMEM>>>(bfp, bip, bgp, bop);
    lstm_persist<<<NBLK, 256, LSTM_SMEM>>>();
    final_k<<<BB, 256>>>(Wlin, blin, out);
}

// round 12
// speedup vs baseline: 5.3833x; 1.1156x over previous
#include <cuda_runtime.h>
#include <cuda_bf16.h>
#include <cuda_fp16.h>
#include <math.h>
#include <stdint.h>

// Problem constants
#define BB 64
#define PP 16
#define TT 256
#define II 256
#define HH 512
#define OO 5
#define KK 4096      // P*I
#define MM 16384     // B*T
#define NT 2048      // 4*H

#define NBLK 128     // persistent recurrence grid (2 groups of 64)
#define LO_SCALE 2048.0f
#define LO_INV   4.8828125e-4f

// ---------------- scratch (device globals) -----------------------------------
__device__ float g_pre[(size_t)TT * 4 * BB * HH];     // [t][gate][b][h]
__device__ __half g_Ah[(size_t)MM * KK];              // fp16 hi of gathered A
__device__ __half g_Al[(size_t)MM * KK];              // fp16 (lo * 2048)
__device__ __half g_Bh[(size_t)NT * KK];              // [n][k] fp16 hi of W_x
__device__ __half g_Wcat[(size_t)NT * 1024];          // [h*4+gate][k'] fp16 recurrence W (2 segs)
__device__ float g_h[2][BB * HH];
__device__ float g_c[BB * HH];
__device__ unsigned g_count2[2] = {0, 0};
__device__ unsigned g_gen2[2] = {0, 0};

// ---------------- helpers ----------------------------------------------------
__device__ __forceinline__ uint32_t smem_u32(const void* p) {
    uint32_t a;
    asm("{ .reg .u64 t; cvta.to.shared.u64 t, %1; cvt.u32.u64 %0, t; }" : "=r"(a) : "l"(p));
    return a;
}
__device__ __forceinline__ void cp16(uint32_t dst, const void* src) {
    asm volatile("cp.async.cg.shared.global [%0], [%1], 16;" :: "r"(dst), "l"(src));
}
__device__ __forceinline__ void cp_commit() {
    asm volatile("cp.async.commit_group;" ::: "memory");
}
__device__ __forceinline__ void ldsm4(uint32_t* r, uint32_t addr) {
    asm volatile("ldmatrix.sync.aligned.m8n8.x4.shared.b16 {%0,%1,%2,%3}, [%4];"
                 : "=r"(r[0]), "=r"(r[1]), "=r"(r[2]), "=r"(r[3]) : "r"(addr));
}
__device__ __forceinline__ void ldsm2(uint32_t* r, uint32_t addr) {
    asm volatile("ldmatrix.sync.aligned.m8n8.x2.shared.b16 {%0,%1}, [%2];"
                 : "=r"(r[0]), "=r"(r[1]) : "r"(addr));
}
__device__ __forceinline__ void mma_f16(float* d, const uint32_t* a, const uint32_t* b) {
    asm volatile(
        "mma.sync.aligned.m16n8k16.row.col.f32.f16.f16.f32 "
        "{%0,%1,%2,%3}, {%4,%5,%6,%7}, {%8,%9}, {%0,%1,%2,%3};"
        : "+f"(d[0]), "+f"(d[1]), "+f"(d[2]), "+f"(d[3])
        : "r"(a[0]), "r"(a[1]), "r"(a[2]), "r"(a[3]), "r"(b[0]), "r"(b[1]));
}
__device__ __forceinline__ uint32_t pack_f16(float a, float b) {
    __half2 v = __floats2half2_rn(a, b);
    return *(uint32_t*)&v;
}
#define SW128(o) ((o) ^ (((o) >> 3) & 0x70))

// ---------------- prep A: gather + fp16 hi/lo(scaled) split ------------------
__global__ void prep_A(const int* __restrict__ x, const float* __restrict__ emb) {
    int v = blockIdx.x * 256 + threadIdx.x;
    int m = v >> 10;
    int k = (v & 1023) << 2;
    int p = k >> 8, i = k & 255;
    int t = m >> 6, b = m & 63;
    int idx = x[(b * PP + p) * TT + t];
    float4 a = make_float4(0.f, 0.f, 0.f, 0.f);
    if (idx != 0) a = *(const float4*)&emb[(size_t)idx * II + i];
    __half h0 = __float2half(a.x);
    __half h1 = __float2half(a.y);
    __half h2 = __float2half(a.z);
    __half h3 = __float2half(a.w);
    __half l0 = __float2half((a.x - __half2float(h0)) * LO_SCALE);
    __half l1 = __float2half((a.y - __half2float(h1)) * LO_SCALE);
    __half l2 = __float2half((a.z - __half2float(h2)) * LO_SCALE);
    __half l3 = __float2half((a.w - __half2float(h3)) * LO_SCALE);
    size_t o = (size_t)m * KK + k;
    *(__half2*)(g_Ah + o)     = __half2(h0, h1);
    *(__half2*)(g_Ah + o + 2) = __half2(h2, h3);
    *(__half2*)(g_Al + o)     = __half2(l0, l1);
    *(__half2*)(g_Al + o + 2) = __half2(l2, l3);
}

// ---------------- prep B: transpose W[k][h] -> B[n][k], fp16 hi only ---------
__global__ void prep_B(const float* __restrict__ Wf, const float* __restrict__ Wi,
                       const float* __restrict__ Wg, const float* __restrict__ Wo) {
    __shared__ float tile[32][33];
    int k0 = blockIdx.x * 32;
    int n0 = blockIdx.y * 32;
    int gate = n0 >> 9;
    int h0 = n0 & 511;
    const float* W = (gate == 0) ? Wf : (gate == 1) ? Wi : (gate == 2) ? Wg : Wo;
    int tx = threadIdx.x, ty = threadIdx.y;
    tile[ty][tx] = W[(size_t)(k0 + ty) * HH + h0 + tx];
    __syncthreads();
    g_Bh[(size_t)(n0 + ty) * KK + k0 + tx] = __float2half(tile[tx][ty]);
}

// ---------------- prep Wcat: recurrence W fp16, both segments identical ------
__global__ void prep_Wcat(const float* __restrict__ Wf, const float* __restrict__ Wi,
                          const float* __restrict__ Wg, const float* __restrict__ Wo) {
    int idx = blockIdx.x * 256 + threadIdx.x;   // < NT*1024
    int c = idx >> 10;
    int kp = idx & 1023;
    int g = c & 3;
    int h = c >> 2;
    int kk = kp & 511;
    const float* W = (g == 0) ? Wf : (g == 1) ? Wi : (g == 2) ? Wg : Wo;
    g_Wcat[(size_t)c * 1024 + kp] = __float2half(W[(size_t)kk * HH + h]);
}

// ---------------- mma.sync GEMM: pre = A @ B^T + bias ------------------------
// 2-term fp16 split: K' = 2*4096 as 128 chunks of 64 ({Ah.Bh, Al'.Bh}).
// 3-stage cp.async pipeline; exact accumulator phase-scaling for the lo term.
#define KCH 64
#define ABUF 16384
#define STAGE (2 * ABUF)
#define GEMM_SMEM (3 * STAGE)          // 98304

__global__ void __launch_bounds__(256, 2)
mma_gemm(const float* __restrict__ bfp, const float* __restrict__ bip,
         const float* __restrict__ bgp, const float* __restrict__ bop) {
    extern __shared__ char smc[];
    uint32_t sbase = smem_u32(smc);
    int tid = threadIdx.x;
    int lane = tid & 31;
    int wid = tid >> 5;
    int mt = blockIdx.y;
    int nt = blockIdx.x;
    int warp_m = wid & 3;
    int warp_n = wid >> 2;

    size_t moff = (size_t)(mt * 128) * KK;
    size_t noff = (size_t)(nt * 128) * KK;
    const __half* Asel[2] = { g_Ah + moff, g_Al + moff };

    float acc[2][8][4];
    #pragma unroll
    for (int mf = 0; mf < 2; mf++)
        #pragma unroll
        for (int nf = 0; nf < 8; nf++)
            #pragma unroll
            for (int e = 0; e < 4; e++) acc[mf][nf][e] = 0.f;

    auto stage = [&](int it) {
        int phase = it >> 6, c = it & 63;
        const __half* A = Asel[phase];
        const __half* B = g_Bh + noff;
        uint32_t ab = sbase + (uint32_t)(it % 3) * STAGE;
        uint32_t bb = ab + ABUF;
        #pragma unroll
        for (int i = 0; i < 4; i++) {
            int v = i * 256 + tid;
            int r = v >> 3, q = v & 7;
            uint32_t so = SW128(r * 128 + q * 16);
            cp16(ab + so, A + (size_t)r * KK + c * KCH + q * 8);
            cp16(bb + so, B + (size_t)r * KK + c * KCH + q * 8);
        }
        cp_commit();
    };

    stage(0);
    stage(1);
    for (int it = 0; it < 128; it++) {
        if (it + 2 < 128) {
            stage(it + 2);
            asm volatile("cp.async.wait_group 2;" ::: "memory");
        } else if (it + 1 < 128) {
            asm volatile("cp.async.wait_group 1;" ::: "memory");
        } else {
            asm volatile("cp.async.wait_group 0;" ::: "memory");
        }
        __syncthreads();

        if (it == 64) {   // phase boundary: acc = Sh -> 2048*Sh (exact)
            #pragma unroll
            for (int mf = 0; mf < 2; mf++)
                #pragma unroll
                for (int nf = 0; nf < 8; nf++)
                    #pragma unroll
                    for (int e = 0; e < 4; e++) acc[mf][nf][e] *= LO_SCALE;
        }

        uint32_t aBase = sbase + (uint32_t)(it % 3) * STAGE;
        uint32_t bBase = aBase + ABUF;
        int arow = lane & 15, asel = lane >> 4;
        int bgrp = lane >> 3, brow = lane & 7;
        #pragma unroll
        for (int ks = 0; ks < 4; ks++) {
            uint32_t a[2][4];
            #pragma unroll
            for (int mf = 0; mf < 2; mf++) {
                int row = warp_m * 32 + mf * 16 + arow;
                ldsm4(a[mf], aBase + SW128(row * 128 + ks * 32 + asel * 16));
            }
            uint32_t b[4][4];
            #pragma unroll
            for (int nfp = 0; nfp < 4; nfp++) {
                int n = warp_n * 64 + nfp * 16 + ((bgrp >> 1) << 3) + brow;
                int kb = ks * 32 + ((bgrp & 1) << 4);
                ldsm4(b[nfp], bBase + SW128(n * 128 + kb));
            }
            #pragma unroll
            for (int mf = 0; mf < 2; mf++)
                #pragma unroll
                for (int nf = 0; nf < 8; nf++)
                    mma_f16(acc[mf][nf], a[mf], &b[nf >> 1][(nf & 1) * 2]);
        }
        __syncthreads();
    }

    // epilogue: acc = 2048*(Sh+Sl) -> *LO_INV, + bias
    int gate = nt >> 2;
    int hbase = (nt & 3) * 128;
    const float* bias = (gate == 0) ? bfp : (gate == 1) ? bip : (gate == 2) ? bgp : bop;
    int grp = lane >> 2, qd = lane & 3;
    #pragma unroll
    for (int mf = 0; mf < 2; mf++) {
        int mrow0 = mt * 128 + warp_m * 32 + mf * 16 + grp;
        #pragma unroll
        for (int half = 0; half < 2; half++) {
            int m = mrow0 + half * 8;
            int t = m >> 6, b = m & 63;
            float* dst = g_pre + ((size_t)(t * 4 + gate) * 64 + b) * 512 + hbase;
            #pragma unroll
            for (int nf = 0; nf < 8; nf++) {
                int col = warp_n * 64 + nf * 8 + qd * 2;
                float2 v;
                v.x = acc[mf][nf][half * 2 + 0] * LO_INV + __ldg(&bias[hbase + col]);
                v.y = acc[mf][nf][half * 2 + 1] * LO_INV + __ldg(&bias[hbase + col + 1]);
                *(float2*)(dst + col) = v;
            }
        }
    }
}

// ---------------- persistent LSTM recurrence (fp16 2-term, split barrier) ----
// 128 blocks in 2 independent groups of 64 (by batch half).
// Block bx: grp = bx>>6 (b0 = grp*32), colgrp = bx&63 (h0 = colgrp*8, c0 = colgrp*32).
#define RW0 0
#define RA0 65536
#define RG0 131072
#define LSTM_SMEM (131072 + 32 * 33 * 4)

__device__ __forceinline__ void grid_barrier2(int grp) {
    __threadfence();
    __syncthreads();
    if (threadIdx.x == 0) {
        unsigned gen = *((volatile unsigned*)&g_gen2[grp]);
        if (atomicAdd(&g_count2[grp], 1u) == 63) {
            g_count2[grp] = 0;
            __threadfence();
            *((volatile unsigned*)&g_gen2[grp]) = gen + 1;
        } else {
            while (*((volatile unsigned*)&g_gen2[grp]) == gen) { }
        }
    }
    __syncthreads();
}

__global__ void __launch_bounds__(256, 1)
lstm_persist() {
    extern __shared__ char smx[];
    uint32_t sb = smem_u32(smx);
    float* sG = (float*)(smx + RG0);

    int tid = threadIdx.x;
    int bx  = blockIdx.x;
    int lane = tid & 31;
    int wid  = tid >> 5;
    int grp2 = bx >> 6;              // barrier group / batch half
    int b0 = grp2 * 32;
    int colgrp = bx & 63;
    int h0 = colgrp * 8;
    int c0 = colgrp * 32;

    // ---- load W' slice once: 32 cols x 1024 fp16, 16 chunks, swizzled
    for (int v = tid; v < 32 * 128; v += 256) {
        int r = v >> 7;
        int g8 = v & 127;
        uint4 w = *(const uint4*)(g_Wcat + (size_t)(c0 + r) * 1024 + g8 * 8);
        int chunk = g8 >> 3;
        uint32_t off = SW128(r * 128 + (g8 & 7) * 16);
        *(uint4*)(smx + RW0 + chunk * 4096 + off) = w;
    }

    // zero h buffer 0 (blocks 0-63 cover rows 0-31; 64-127 rows 32-63)
    g_h[0][bx * 256 + tid] = 0.f;

    int mhalf = wid & 1;
    int nq = wid >> 1;
    int bl = tid >> 3;
    int phl = tid & 7;
    float c_reg = 0.f;

    grid_barrier2(grp2);

    for (int t = 0; t < TT; t++) {
        const float* hsrc = g_h[t & 1];
        // ---- stage A' = [Hh, Hl*2048] (32 rows x 512 k)
        for (int v = tid; v < 2048; v += 256) {
            int r = v >> 6;
            int gq = v & 63;
            int k = gq * 8;
            float4 x0 = __ldcg((const float4*)&hsrc[(b0 + r) * HH + k]);
            float4 x1 = __ldcg((const float4*)&hsrc[(b0 + r) * HH + k + 4]);
            uint4 HI, LO;
            HI.x = pack_f16(x0.x, x0.y); HI.y = pack_f16(x0.z, x0.w);
            HI.z = pack_f16(x1.x, x1.y); HI.w = pack_f16(x1.z, x1.w);
            __half2 h01 = *(__half2*)&HI.x;
            __half2 h23 = *(__half2*)&HI.y;
            __half2 h45 = *(__half2*)&HI.z;
            __half2 h67 = *(__half2*)&HI.w;
            LO.x = pack_f16((x0.x - __half2float(h01.x)) * LO_SCALE,
                            (x0.y - __half2float(h01.y)) * LO_SCALE);
            LO.y = pack_f16((x0.z - __half2float(h23.x)) * LO_SCALE,
                            (x0.w - __half2float(h23.y)) * LO_SCALE);
            LO.z = pack_f16((x1.x - __half2float(h45.x)) * LO_SCALE,
                            (x1.y - __half2float(h45.y)) * LO_SCALE);
            LO.w = pack_f16((x1.z - __half2float(h67.x)) * LO_SCALE,
                            (x1.w - __half2float(h67.y)) * LO_SCALE);
            int chunk = gq >> 3;
            uint32_t off = SW128(r * 128 + (gq & 7) * 16);
            *(uint4*)(smx + RA0 + chunk * 4096 + off) = HI;         // seg0: Hh
            *(uint4*)(smx + RA0 + (chunk + 8) * 4096 + off) = LO;   // seg1: Hl*2048
        }
        const float* pre_t = g_pre + (size_t)t * 4 * BB * HH;
        float pf = __ldcg(&pre_t[((0 * 64) + b0 + bl) * HH + h0 + phl]);
        float pi = __ldcg(&pre_t[((1 * 64) + b0 + bl) * HH + h0 + phl]);
        float pg = __ldcg(&pre_t[((2 * 64) + b0 + bl) * HH + h0 + phl]);
        float po = __ldcg(&pre_t[((3 * 64) + b0 + bl) * HH + h0 + phl]);
        __syncthreads();

        // ---- gates mma: 16x8 warp tile, K' = 1024 (2 segments of 512)
        float acc[4] = {0.f, 0.f, 0.f, 0.f};
        int arow = mhalf * 16 + (lane & 15);
        int asel = lane >> 4;
        int ln = lane & 15;
        int brow = nq * 8 + (ln & 7);
        int bsel = (ln >> 3) & 1;
        #pragma unroll 4
        for (int kk16 = 0; kk16 < 32; kk16++) {
            int chunk = kk16 >> 2;
            int kb = (kk16 & 3) * 32;
            uint32_t a[4], b2[2];
            ldsm4(a, sb + RA0 + chunk * 4096 + SW128(arow * 128 + kb + asel * 16));
            ldsm2(b2, sb + RW0 + chunk * 4096 + SW128(brow * 128 + kb + bsel * 16));
            mma_f16(acc, a, b2);
        }
        #pragma unroll
        for (int e = 0; e < 4; e++) acc[e] *= LO_SCALE;   // exact phase scale
        #pragma unroll 4
        for (int kk16 = 32; kk16 < 64; kk16++) {
            int chunk = kk16 >> 2;          // 8..15 (A' lo seg)
            int wchunk = (kk16 - 32) >> 2;  // W repeats seg0
            int kb = (kk16 & 3) * 32;
            uint32_t a[4], b2[2];
            ldsm4(a, sb + RA0 + chunk * 4096 + SW128(arow * 128 + kb + asel * 16));
            ldsm2(b2, sb + RW0 + wchunk * 4096 + SW128(brow * 128 + kb + bsel * 16));
            mma_f16(acc, a, b2);
        }
        // ---- publish gates (undo scale)
        int rw = mhalf * 16 + (lane >> 2);
        int cw = nq * 8 + (lane & 3) * 2;
        sG[rw * 33 + cw]           = acc[0] * LO_INV;
        sG[rw * 33 + cw + 1]       = acc[1] * LO_INV;
        sG[(rw + 8) * 33 + cw]     = acc[2] * LO_INV;
        sG[(rw + 8) * 33 + cw + 1] = acc[3] * LO_INV;
        __syncthreads();

        float gf = pf + sG[bl * 33 + phl * 4 + 0];
        float gi = pi + sG[bl * 33 + phl * 4 + 1];
        float gg = pg + sG[bl * 33 + phl * 4 + 2];
        float go = po + sG[bl * 33 + phl * 4 + 3];
        float f  = 1.f / (1.f + expf(-gf));
        float i  = 1.f / (1.f + expf(-gi));
        float g  = tanhf(gg);
        float o  = 1.f / (1.f + expf(-go));
        c_reg = f * c_reg + i * g;
        float hnew = o * tanhf(c_reg);
        __stcg(&g_h[(t + 1) & 1][(b0 + bl) * HH + h0 + phl], hnew);

        grid_barrier2(grp2);
    }
    g_c[(b0 + bl) * HH + h0 + phl] = c_reg;
}

// ---------------- final: out = h @ W_lin + b_lin; emit (out, h, c) ----------
__global__ void final_k(const float* __restrict__ Wlin, const float* __restrict__ blin,
                        float* __restrict__ out) {
    int b = blockIdx.x;
    int tid = threadIdx.x;
    const float* h = g_h[0];
    const float* c = g_c;

    float* out_h = out + BB * OO;
    float* out_c = out + BB * OO + BB * HH;
    for (int v = tid; v < HH; v += 256) {
        out_h[b * HH + v] = h[b * HH + v];
        out_c[b * HH + v] = c[b * HH + v];
    }
    __shared__ float red[256 * OO];
    float p[OO];
    #pragma unroll
    for (int o = 0; o < OO; o++) p[o] = 0.f;
    for (int k = tid; k < HH; k += 256) {
        float hv = h[b * HH + k];
        #pragma unroll
        for (int o = 0; o < OO; o++) p[o] += hv * Wlin[k * OO + o];
    }
    #pragma unroll
    for (int o = 0; o < OO; o++) red[tid * OO + o] = p[o];
    __syncthreads();
    for (int s = 128; s > 0; s >>= 1) {
        if (tid < s)
            #pragma unroll
            for (int o = 0; o < OO; o++) red[tid * OO + o] += red[(tid + s) * OO + o];
        __syncthreads();
    }
    if (tid < OO) out[b * OO + tid] = red[tid] + blin[tid];
}

// ---------------- host launcher ---------------------------------------------
extern "C" void kernel_launch(void* const* d_in, const int* in_sizes, int n_in,
                              void* d_out, int out_size) {
    const int*   x    = (const int*)d_in[0];
    const float* emb  = (const float*)d_in[1];
    const float* Wfx  = (const float*)d_in[2];
    const float* Wfh  = (const float*)d_in[3];
    const float* bfp  = (const float*)d_in[4];
    const float* Wix  = (const float*)d_in[5];
    const float* Wih  = (const float*)d_in[6];
    const float* bip  = (const float*)d_in[7];
    const float* Wgx  = (const float*)d_in[8];
    const float* Wgh  = (const float*)d_in[9];
    const float* bgp  = (const float*)d_in[10];
    const float* Wox  = (const float*)d_in[11];
    const float* Woh  = (const float*)d_in[12];
    const float* bop  = (const float*)d_in[13];
    const float* Wlin = (const float*)d_in[14];
    const float* blin = (const float*)d_in[15];
    float* out = (float*)d_out;

    cudaFuncSetAttribute(mma_gemm, cudaFuncAttributeMaxDynamicSharedMemorySize, GEMM_SMEM);
    cudaFuncSetAttribute(lstm_persist, cudaFuncAttributeMaxDynamicSharedMemorySize, LSTM_SMEM);

    prep_A<<<65536, 256>>>(x, emb);
    prep_B<<<dim3(KK / 32, NT / 32), dim3(32, 32)>>>(Wfx, Wix, Wgx, Wox);
    prep_Wcat<<<NT * 4, 256>>>(Wfh, Wih, Wgh, Woh);
    mma_gemm<<<dim3(NT / 128, MM / 128), 256, GEMM_SMEM>>>(bfp, bip, bgp, bop);
    lstm_persist<<<NBLK, 256, LSTM_SMEM>>>();
    final_k<<<BB, 256>>>(Wlin, blin, out);
}